// round 7
// baseline (speedup 1.0000x reference)
#include <cuda_runtime.h>
#include <cuda_bf16.h>
#include <math.h>
#include <stdint.h>

// Problem constants
#define B_   2
#define T_   2048
#define E_   2048
#define H_   16
#define HKV_ 4
#define D_   128
#define ROWS (B_ * T_)          // 4096
#define QCOLS (H_ * D_)         // 2048
#define KCOLS (HKV_ * D_)       // 512

// ---------------------------------------------------------------------------
// Scratch (allocation-free: device globals)
// ---------------------------------------------------------------------------
__device__ __align__(1024) float g_xr [(size_t)ROWS * E_];
__device__ __align__(1024) float g_Wq [(size_t)E_ * QCOLS];
__device__ __align__(1024) float g_Wk [(size_t)E_ * KCOLS];
__device__ __align__(1024) float g_Wv [(size_t)E_ * KCOLS];
__device__ __align__(1024) float g_Wo [(size_t)QCOLS * E_];
__device__ __align__(1024) float g_Q  [(size_t)ROWS * QCOLS];
__device__ __align__(1024) float g_K  [(size_t)ROWS * KCOLS];
__device__ __align__(1024) float g_V  [(size_t)ROWS * KCOLS];
__device__ __align__(1024) float g_ctx[(size_t)ROWS * QCOLS];
__device__ __align__(1024) float g_rcos[T_ * 64];
__device__ __align__(1024) float g_rsin[T_ * 64];

// ---------------------------------------------------------------------------
// Helpers
// ---------------------------------------------------------------------------
__device__ __forceinline__ float rna_tf32(float x) {
    uint32_t y;
    asm("cvt.rna.tf32.f32 %0, %1;" : "=r"(y) : "f"(x));
    return __uint_as_float(y);
}
__device__ __forceinline__ uint32_t smem_u32(const void* p) {
    uint32_t a;
    asm("{ .reg .u64 t; cvta.to.shared.u64 t, %1; cvt.u32.u64 %0, t; }" : "=r"(a) : "l"(p));
    return a;
}
__device__ __forceinline__ void cp_async16(uint32_t saddr, const void* gptr) {
    asm volatile("cp.async.cg.shared.global [%0], [%1], 16;" :: "r"(saddr), "l"(gptr));
}
#define CP_COMMIT() asm volatile("cp.async.commit_group;" ::: "memory")
#define CP_WAIT(n)  asm volatile("cp.async.wait_group %0;" :: "n"(n) : "memory")

__device__ __forceinline__ void mma_tf32(float* c, const uint32_t* a, const uint32_t* b) {
    asm volatile(
        "mma.sync.aligned.m16n8k8.row.col.f32.tf32.tf32.f32 "
        "{%0,%1,%2,%3}, {%4,%5,%6,%7}, {%8,%9}, {%0,%1,%2,%3};"
        : "+f"(c[0]), "+f"(c[1]), "+f"(c[2]), "+f"(c[3])
        : "r"(a[0]), "r"(a[1]), "r"(a[2]), "r"(a[3]), "r"(b[0]), "r"(b[1]));
}

// ---------------------------------------------------------------------------
// Rope cos/sin table (double-precision source, fp32 table).
// ---------------------------------------------------------------------------
__global__ void rope_table(float* __restrict__ ct, float* __restrict__ st) {
    int idx = blockIdx.x * blockDim.x + threadIdx.x;
    if (idx >= T_ * 64) return;
    int t = idx >> 6, i = idx & 63;
    double w = pow(10000.0, -(double)i / 64.0);
    double ds, dc;
    sincos((double)t * w, &ds, &dc);
    ct[idx] = (float)dc;
    st[idx] = (float)ds;
}

// ---------------------------------------------------------------------------
// One-shot prep: tf32-RN rounding copy of all 5 operand tensors.
// ---------------------------------------------------------------------------
#define P_S0 (ROWS * E_ / 4)
#define P_S1 (P_S0 + E_ * QCOLS / 4)
#define P_S2 (P_S1 + E_ * KCOLS / 4)
#define P_S3 (P_S2 + E_ * KCOLS / 4)
#define P_S4 (P_S3 + QCOLS * E_ / 4)

__global__ void prep_all(const float* __restrict__ x,  const float* __restrict__ wq,
                         const float* __restrict__ wk, const float* __restrict__ wv,
                         const float* __restrict__ wo,
                         float* xr, float* wqr, float* wkr, float* wvr, float* wor) {
    int idx = blockIdx.x * blockDim.x + threadIdx.x;
    const float4* in; float4* out; int j;
    if      (idx < P_S0) { in = (const float4*)x;  out = (float4*)xr;  j = idx; }
    else if (idx < P_S1) { in = (const float4*)wq; out = (float4*)wqr; j = idx - P_S0; }
    else if (idx < P_S2) { in = (const float4*)wk; out = (float4*)wkr; j = idx - P_S1; }
    else if (idx < P_S3) { in = (const float4*)wv; out = (float4*)wvr; j = idx - P_S2; }
    else if (idx < P_S4) { in = (const float4*)wo; out = (float4*)wor; j = idx - P_S3; }
    else return;
    float4 v = in[j];
    v.x = rna_tf32(v.x); v.y = rna_tf32(v.y); v.z = rna_tf32(v.z); v.w = rna_tf32(v.w);
    out[j] = v;
}

// ---------------------------------------------------------------------------
// TF32 mma.sync GEMM, 3-way dispatch, 3-stage cp.async, 2 CTAs/SM.
// C[M,N] = A[M,K] @ B[K,N]. Tile 128x128x32, 256 threads (8 warps, 4x2).
// mode: 0 plain store, 1 round, 2 rope+scale+round (Q), 3 rope+round (K).
// ---------------------------------------------------------------------------
#define GBM 128
#define GBN 128
#define GBK 32
#define GAST 36
#define GBST 136
#define GSTAGES 3
#define GA_FLOATS (GBM * GAST)
#define GB_FLOATS (GBK * GBST)
#define GSTAGE_FLOATS (GA_FLOATS + GB_FLOATS)
#define GSMEM_BYTES (GSTAGES * GSTAGE_FLOATS * 4)   // 107520

__global__ __launch_bounds__(256, 2) void gemm_mma(
    const float* __restrict__ A,
    const float* __restrict__ B1, float* __restrict__ C1, int mode1, int nblk1, int N1,
    const float* __restrict__ B2, float* __restrict__ C2, int mode2, int nblk2, int N2,
    const float* __restrict__ B3, float* __restrict__ C3, int mode3, int N3,
    int K, const float* __restrict__ ct, const float* __restrict__ st)
{
    extern __shared__ __align__(16) float smem[];
    const int tid = threadIdx.x;
    const int wid = tid >> 5, lane = tid & 31;
    const int warpM = wid & 3, warpN = wid >> 2;
    const int bx = blockIdx.x;

    const float* Bw; float* C; int mode, n0, N;
    if (bx < nblk1)              { Bw = B1; C = C1; mode = mode1; N = N1; n0 = bx * GBN; }
    else if (bx < nblk1 + nblk2) { Bw = B2; C = C2; mode = mode2; N = N2; n0 = (bx - nblk1) * GBN; }
    else                         { Bw = B3; C = C3; mode = mode3; N = N3; n0 = (bx - nblk1 - nblk2) * GBN; }

    const int m0 = blockIdx.y * GBM;
    const int nch = K / GBK;
    const int lr = lane >> 2, lc = lane & 3;

    float acc[2][8][4];
#pragma unroll
    for (int i = 0; i < 2; i++)
#pragma unroll
        for (int j = 0; j < 8; j++)
#pragma unroll
            for (int q = 0; q < 4; q++) acc[i][j][q] = 0.f;

    auto load_chunk = [&](int c, int s) {
        float* As = smem + s * GSTAGE_FLOATS;
        float* Bs = As + GA_FLOATS;
        const uint32_t as_base = smem_u32(As);
        const uint32_t bs_base = smem_u32(Bs);
#pragma unroll
        for (int i = 0; i < 4; i++) {
            int ci = tid + i * 256;
            int row = ci >> 3, ch = ci & 7;
            cp_async16(as_base + (row * GAST + ch * 4) * 4,
                       A + (size_t)(m0 + row) * K + c * GBK + ch * 4);
        }
#pragma unroll
        for (int i = 0; i < 4; i++) {
            int ci = tid + i * 256;
            int row = ci >> 5, ch = ci & 31;
            cp_async16(bs_base + (row * GBST + ch * 4) * 4,
                       Bw + (size_t)(c * GBK + row) * N + n0 + ch * 4);
        }
    };

#pragma unroll
    for (int s = 0; s < GSTAGES - 1; s++) { load_chunk(s, s); CP_COMMIT(); }

    for (int c = 0; c < nch; c++) {
        CP_WAIT(GSTAGES - 2);
        __syncthreads();

        int pc = c + GSTAGES - 1;
        if (pc < nch) load_chunk(pc, pc % GSTAGES);
        CP_COMMIT();

        const float* As = smem + (c % GSTAGES) * GSTAGE_FLOATS;
        const float* Bs = As + GA_FLOATS;
        const uint32_t* Asu = (const uint32_t*)As;
        const uint32_t* Bsu = (const uint32_t*)Bs;

#pragma unroll
        for (int kk = 0; kk < 4; kk++) {
            uint32_t afr[2][4], bfr[8][2];
#pragma unroll
            for (int mt = 0; mt < 2; mt++) {
                int row = warpM * 32 + mt * 16 + lr;
                int col = kk * 8 + lc;
                afr[mt][0] = Asu[row * GAST + col];
                afr[mt][1] = Asu[(row + 8) * GAST + col];
                afr[mt][2] = Asu[row * GAST + col + 4];
                afr[mt][3] = Asu[(row + 8) * GAST + col + 4];
            }
#pragma unroll
            for (int nt = 0; nt < 8; nt++) {
                int n = warpN * 64 + nt * 8 + lr;
                int k = kk * 8 + lc;
                bfr[nt][0] = Bsu[k * GBST + n];
                bfr[nt][1] = Bsu[(k + 4) * GBST + n];
            }
#pragma unroll
            for (int mt = 0; mt < 2; mt++)
#pragma unroll
                for (int nt = 0; nt < 8; nt++)
                    mma_tf32(acc[mt][nt], afr[mt], bfr[nt]);
        }
        __syncthreads();
    }

    // ---- fused epilogue ----
#pragma unroll
    for (int mt = 0; mt < 2; mt++) {
        int rbase = m0 + warpM * 32 + mt * 16 + lr;
#pragma unroll
        for (int nt = 0; nt < 8; nt++) {
            int cbase = n0 + warpN * 64 + nt * 8 + lc * 2;
            float4 v = make_float4(acc[mt][nt][0], acc[mt][nt][1],
                                   acc[mt][nt][2], acc[mt][nt][3]);
            if (mode >= 2) {
                int i  = (cbase & 127) >> 1;
                int t0 = rbase & (T_ - 1);
                int t1 = (rbase + 8) & (T_ - 1);
                float c0 = ct[(t0 << 6) + i], s0 = st[(t0 << 6) + i];
                float c1 = ct[(t1 << 6) + i], s1 = st[(t1 << 6) + i];
                float scale = (mode == 2) ? 0.08838834764831845f : 1.0f;
                float x0 = (v.x * c0 - v.y * s0) * scale;
                float y0 = (v.x * s0 + v.y * c0) * scale;
                float x1 = (v.z * c1 - v.w * s1) * scale;
                float y1 = (v.z * s1 + v.w * c1) * scale;
                v = make_float4(rna_tf32(x0), rna_tf32(y0), rna_tf32(x1), rna_tf32(y1));
            } else if (mode == 1) {
                v.x = rna_tf32(v.x); v.y = rna_tf32(v.y);
                v.z = rna_tf32(v.z); v.w = rna_tf32(v.w);
            }
            *(float2*)(C + (size_t)rbase * N + cbase)       = make_float2(v.x, v.y);
            *(float2*)(C + (size_t)(rbase + 8) * N + cbase) = make_float2(v.z, v.w);
        }
    }
}

// ---------------------------------------------------------------------------
// Causal flash attention, split-D: CTA = 64 query rows, 8 warps =
// 4 row-pairs x 2 D-halves. Each warp: Q-frags + O-accum for its 64-dim half
// only (32+32 regs); S partials exchanged via smem (commutative add -> both
// warps bit-identical). Single-buffered K/V; 2 CTAs/SM hide load latency.
// ---------------------------------------------------------------------------
#define FBM 64
#define KST 132
#define VST 136
#define PST 68
#define FKS_FLOATS (64 * KST)                 // 8448
#define FVS_FLOATS (64 * VST)                 // 8704
#define FBUF_FLOATS (8 * 16 * PST)            // 8704
#define FA_SMEM_BYTES ((FKS_FLOATS + FVS_FLOATS + FBUF_FLOATS) * 4)  // 103424

__global__ __launch_bounds__(256, 2) void flash_mma(const float* __restrict__ Q,
                                                    const float* __restrict__ Km,
                                                    const float* __restrict__ Vm,
                                                    float* __restrict__ ctx) {
    extern __shared__ __align__(16) float sm[];
    float* Ks  = sm;
    float* Vs  = sm + FKS_FLOATS;
    float* Buf = Vs + FVS_FLOATS;

    const int tid = threadIdx.x;
    const int wid = tid >> 5, lane = tid & 31;
    const int lr = lane >> 2, lc = lane & 3;
    const int pr = wid >> 1;          // row-pair 0..3
    const int dh = wid & 1;           // D-half 0..1
    const int m0 = (int)(gridDim.x - 1 - blockIdx.x) * FBM;   // heavy first
    const int h = blockIdx.y, b = blockIdx.z;
    const int kvh = h >> 2;

    float* Pmy = Buf + (pr * 2 + dh) * 16 * PST;        // my exchange buffer
    float* Pot = Buf + (pr * 2 + (1 - dh)) * 16 * PST;  // pair's buffer
    float* Pp  = Buf + (pr * 2 + 1) * 16 * PST;         // shared P (buf[pr][1])
    uint32_t* Pmyu = (uint32_t*)Pmy;
    uint32_t* Ppu  = (uint32_t*)Pp;

    // ---- Q fragments for my D-half (staged through my buffer) ----
    uint32_t qa[8][4];
    {
        const float* qsrc = Q + (size_t)(b * T_ + m0 + pr * 16) * QCOLS + h * 128 + dh * 64;
#pragma unroll
        for (int i = 0; i < 8; i++) {
            int task = lane + i * 32;           // 256 float4 tasks (16 rows x 16)
            int row = task >> 4, c4 = task & 15;
            float4 v = *(const float4*)(qsrc + (size_t)row * QCOLS + c4 * 4);
            *(float4*)&Pmy[row * PST + c4 * 4] = v;
        }
        __syncwarp();
#pragma unroll
        for (int k8 = 0; k8 < 8; k8++) {
            qa[k8][0] = Pmyu[lr * PST + k8 * 8 + lc];
            qa[k8][1] = Pmyu[(lr + 8) * PST + k8 * 8 + lc];
            qa[k8][2] = Pmyu[lr * PST + k8 * 8 + lc + 4];
            qa[k8][3] = Pmyu[(lr + 8) * PST + k8 * 8 + lc + 4];
        }
    }

    float oacc[8][4];
#pragma unroll
    for (int i = 0; i < 8; i++)
#pragma unroll
        for (int q = 0; q < 4; q++) oacc[i][q] = 0.f;
    float m_i[2] = {-1e30f, -1e30f};
    float l_i[2] = {0.f, 0.f};

    const int ntiles = m0 / 64 + 1;
    const int rowg0 = m0 + pr * 16 + lr;
    const int rowg1 = rowg0 + 8;

    for (int t = 0; t < ntiles; t++) {
        __syncthreads();   // prior tile's smem readers done before overwrite

        // ---- load K/V tile t (single buffer; co-resident CTA hides latency) ----
        {
            const float* kb = Km + (size_t)(b * T_ + t * 64) * KCOLS + kvh * 128;
            const float* vb = Vm + (size_t)(b * T_ + t * 64) * KCOLS + kvh * 128;
            uint32_t ka = smem_u32(Ks);
            uint32_t va = smem_u32(Vs);
#pragma unroll
            for (int i = 0; i < 8; i++) {
                int task = tid + i * 256;
                int row = task >> 5, ch = task & 31;
                cp_async16(ka + (row * KST + ch * 4) * 4, kb + (size_t)row * KCOLS + ch * 4);
            }
#pragma unroll
            for (int i = 0; i < 8; i++) {
                int task = tid + i * 256;
                int row = task >> 5, ch = task & 31;
                cp_async16(va + (row * VST + ch * 4) * 4, vb + (size_t)row * KCOLS + ch * 4);
            }
        }
        CP_COMMIT();
        CP_WAIT(0);
        __syncthreads();

        // ---- S_partial = Q_half K_half^T ----
        const uint32_t* Ksu = (const uint32_t*)Ks;
        const uint32_t* Vsu = (const uint32_t*)Vs;
        float sacc[8][4];
#pragma unroll
        for (int nt = 0; nt < 8; nt++)
#pragma unroll
            for (int q = 0; q < 4; q++) sacc[nt][q] = 0.f;

#pragma unroll
        for (int kk = 0; kk < 8; kk++) {
            uint32_t bfr[8][2];
#pragma unroll
            for (int nt = 0; nt < 8; nt++) {
                bfr[nt][0] = Ksu[(nt * 8 + lr) * KST + dh * 64 + kk * 8 + lc];
                bfr[nt][1] = Ksu[(nt * 8 + lr) * KST + dh * 64 + kk * 8 + lc + 4];
            }
#pragma unroll
            for (int nt = 0; nt < 8; nt++)
                mma_tf32(sacc[nt], qa[kk], bfr[nt]);
        }

        // ---- exchange partials with pair warp ----
#pragma unroll
        for (int nt = 0; nt < 8; nt++) {
            *(float2*)&Pmy[lr * PST + nt * 8 + 2 * lc]       = make_float2(sacc[nt][0], sacc[nt][1]);
            *(float2*)&Pmy[(lr + 8) * PST + nt * 8 + 2 * lc] = make_float2(sacc[nt][2], sacc[nt][3]);
        }
        __syncthreads();
#pragma unroll
        for (int nt = 0; nt < 8; nt++) {
            float2 o0 = *(const float2*)&Pot[lr * PST + nt * 8 + 2 * lc];
            float2 o1 = *(const float2*)&Pot[(lr + 8) * PST + nt * 8 + 2 * lc];
            sacc[nt][0] += o0.x; sacc[nt][1] += o0.y;
            sacc[nt][2] += o1.x; sacc[nt][3] += o1.y;
        }

        // ---- causal mask (only diagonal tile) ----
        if (t == ntiles - 1) {
#pragma unroll
            for (int nt = 0; nt < 8; nt++) {
                int colg = t * 64 + nt * 8 + 2 * lc;
                if (colg     > rowg0) sacc[nt][0] = -1e30f;
                if (colg + 1 > rowg0) sacc[nt][1] = -1e30f;
                if (colg     > rowg1) sacc[nt][2] = -1e30f;
                if (colg + 1 > rowg1) sacc[nt][3] = -1e30f;
            }
        }

        // ---- online softmax (identical in both pair warps) ----
        float rmax0 = -1e30f, rmax1 = -1e30f;
#pragma unroll
        for (int nt = 0; nt < 8; nt++) {
            rmax0 = fmaxf(rmax0, fmaxf(sacc[nt][0], sacc[nt][1]));
            rmax1 = fmaxf(rmax1, fmaxf(sacc[nt][2], sacc[nt][3]));
        }
        rmax0 = fmaxf(rmax0, __shfl_xor_sync(0xffffffffu, rmax0, 1));
        rmax0 = fmaxf(rmax0, __shfl_xor_sync(0xffffffffu, rmax0, 2));
        rmax1 = fmaxf(rmax1, __shfl_xor_sync(0xffffffffu, rmax1, 1));
        rmax1 = fmaxf(rmax1, __shfl_xor_sync(0xffffffffu, rmax1, 2));

        float mnew0 = fmaxf(m_i[0], rmax0);
        float mnew1 = fmaxf(m_i[1], rmax1);
        float alpha0 = __expf(m_i[0] - mnew0);
        float alpha1 = __expf(m_i[1] - mnew1);

        float rsum0 = 0.f, rsum1 = 0.f;
#pragma unroll
        for (int nt = 0; nt < 8; nt++) {
            float p0 = rna_tf32(__expf(sacc[nt][0] - mnew0));
            float p1 = rna_tf32(__expf(sacc[nt][1] - mnew0));
            float p2 = rna_tf32(__expf(sacc[nt][2] - mnew1));
            float p3 = rna_tf32(__expf(sacc[nt][3] - mnew1));
            rsum0 += p0 + p1;
            rsum1 += p2 + p3;
            if (dh == 0) {
                *(float2*)&Pp[lr * PST + nt * 8 + 2 * lc]       = make_float2(p0, p1);
                *(float2*)&Pp[(lr + 8) * PST + nt * 8 + 2 * lc] = make_float2(p2, p3);
            }
        }
        rsum0 += __shfl_xor_sync(0xffffffffu, rsum0, 1);
        rsum0 += __shfl_xor_sync(0xffffffffu, rsum0, 2);
        rsum1 += __shfl_xor_sync(0xffffffffu, rsum1, 1);
        rsum1 += __shfl_xor_sync(0xffffffffu, rsum1, 2);

        l_i[0] = l_i[0] * alpha0 + rsum0;
        l_i[1] = l_i[1] * alpha1 + rsum1;
        m_i[0] = mnew0;
        m_i[1] = mnew1;
#pragma unroll
        for (int nt = 0; nt < 8; nt++) {
            oacc[nt][0] *= alpha0; oacc[nt][1] *= alpha0;
            oacc[nt][2] *= alpha1; oacc[nt][3] *= alpha1;
        }
        __syncthreads();   // P visible to pair warp

        // ---- O_half += P V_half ----
#pragma unroll
        for (int kk = 0; kk < 8; kk++) {
            uint32_t pa[4];
            pa[0] = Ppu[lr * PST + kk * 8 + lc];
            pa[1] = Ppu[(lr + 8) * PST + kk * 8 + lc];
            pa[2] = Ppu[lr * PST + kk * 8 + lc + 4];
            pa[3] = Ppu[(lr + 8) * PST + kk * 8 + lc + 4];
#pragma unroll
            for (int nt = 0; nt < 8; nt++) {
                uint32_t bfr[2];
                bfr[0] = Vsu[(kk * 8 + lc) * VST + dh * 64 + nt * 8 + lr];
                bfr[1] = Vsu[(kk * 8 + lc + 4) * VST + dh * 64 + nt * 8 + lr];
                mma_tf32(oacc[nt], pa, bfr);
            }
        }
    }

    // ---- epilogue ----
    float inv0 = 1.0f / l_i[0];
    float inv1 = 1.0f / l_i[1];
    float* c0 = ctx + (size_t)(b * T_ + rowg0) * QCOLS + h * 128 + dh * 64;
    float* c1 = ctx + (size_t)(b * T_ + rowg1) * QCOLS + h * 128 + dh * 64;
#pragma unroll
    for (int nt = 0; nt < 8; nt++) {
        int col = nt * 8 + 2 * lc;
        *(float2*)(c0 + col) = make_float2(rna_tf32(oacc[nt][0] * inv0),
                                           rna_tf32(oacc[nt][1] * inv0));
        *(float2*)(c1 + col) = make_float2(rna_tf32(oacc[nt][2] * inv1),
                                           rna_tf32(oacc[nt][3] * inv1));
    }
}

// ---------------------------------------------------------------------------
// Host
// ---------------------------------------------------------------------------
extern "C" void kernel_launch(void* const* d_in, const int* in_sizes, int n_in,
                              void* d_out, int out_size) {
    const float* x    = (const float*)d_in[0];
    const float* Wq   = (const float*)d_in[1];
    const float* Wk   = (const float*)d_in[2];
    const float* Wv   = (const float*)d_in[3];
    const float* Wout = (const float*)d_in[4];
    float* out = (float*)d_out;

    float *xr, *Wqr, *Wkr, *Wvr, *Wor, *Qb, *Kb, *Vb, *Cb, *ctab, *stab;
    cudaGetSymbolAddress((void**)&xr,  g_xr);
    cudaGetSymbolAddress((void**)&Wqr, g_Wq);
    cudaGetSymbolAddress((void**)&Wkr, g_Wk);
    cudaGetSymbolAddress((void**)&Wvr, g_Wv);
    cudaGetSymbolAddress((void**)&Wor, g_Wo);
    cudaGetSymbolAddress((void**)&Qb,  g_Q);
    cudaGetSymbolAddress((void**)&Kb,  g_K);
    cudaGetSymbolAddress((void**)&Vb,  g_V);
    cudaGetSymbolAddress((void**)&Cb,  g_ctx);
    cudaGetSymbolAddress((void**)&ctab, g_rcos);
    cudaGetSymbolAddress((void**)&stab, g_rsin);

    cudaFuncSetAttribute(gemm_mma, cudaFuncAttributeMaxDynamicSharedMemorySize, GSMEM_BYTES);
    cudaFuncSetAttribute(flash_mma, cudaFuncAttributeMaxDynamicSharedMemorySize, FA_SMEM_BYTES);

    // 1) prep: round all operands to tf32-RN
    prep_all<<<(P_S4 + 255) / 256, 256>>>(x, Wq, Wk, Wv, Wout, xr, Wqr, Wkr, Wvr, Wor);

    // 2) rope table
    rope_table<<<(T_ * 64 + 255) / 256, 256>>>(ctab, stab);

    // 3) Q + K + V projections in ONE launch
    gemm_mma<<<dim3(24, ROWS / GBM), 256, GSMEM_BYTES>>>(
        xr,
        Wqr, Qb, 2, QCOLS / GBN, QCOLS,
        Wkr, Kb, 3, KCOLS / GBN, KCOLS,
        Wvr, Vb, 1, KCOLS,
        E_, ctab, stab);

    // 4) attention (split-D flash, 2 CTAs/SM)
    flash_mma<<<dim3(T_ / FBM, H_, B_), 256, FA_SMEM_BYTES>>>(Qb, Kb, Vb, Cb);

    // 5) output projection
    gemm_mma<<<dim3(E_ / GBN, ROWS / GBM), 256, GSMEM_BYTES>>>(
        Cb,
        Wor, out, 0, E_ / GBN, E_,
        Wor, out, 0, 0, E_,
        Wor, out, 0, E_,
        QCOLS, ctab, stab);
}

// round 8
// speedup vs baseline: 1.0855x; 1.0855x over previous
#include <cuda_runtime.h>
#include <cuda_bf16.h>
#include <math.h>
#include <stdint.h>

// Problem constants
#define B_   2
#define T_   2048
#define E_   2048
#define H_   16
#define HKV_ 4
#define D_   128
#define ROWS (B_ * T_)          // 4096
#define QCOLS (H_ * D_)         // 2048
#define KCOLS (HKV_ * D_)       // 512

// ---------------------------------------------------------------------------
// Scratch (allocation-free: device globals). Weights stored TRANSPOSED [N][K].
// ---------------------------------------------------------------------------
__device__ __align__(1024) float g_xr [(size_t)ROWS * E_];
__device__ __align__(1024) float g_WqT[(size_t)QCOLS * E_];
__device__ __align__(1024) float g_WkT[(size_t)KCOLS * E_];
__device__ __align__(1024) float g_WvT[(size_t)KCOLS * E_];
__device__ __align__(1024) float g_WoT[(size_t)E_ * QCOLS];
__device__ __align__(1024) float g_Q  [(size_t)ROWS * QCOLS];
__device__ __align__(1024) float g_K  [(size_t)ROWS * KCOLS];
__device__ __align__(1024) float g_V  [(size_t)ROWS * KCOLS];
__device__ __align__(1024) float g_ctx[(size_t)ROWS * QCOLS];
__device__ __align__(1024) float g_rcos[T_ * 64];
__device__ __align__(1024) float g_rsin[T_ * 64];

// ---------------------------------------------------------------------------
// Helpers
// ---------------------------------------------------------------------------
__device__ __forceinline__ float rna_tf32(float x) {
    uint32_t y;
    asm("cvt.rna.tf32.f32 %0, %1;" : "=r"(y) : "f"(x));
    return __uint_as_float(y);
}
__device__ __forceinline__ uint32_t smem_u32(const void* p) {
    uint32_t a;
    asm("{ .reg .u64 t; cvta.to.shared.u64 t, %1; cvt.u32.u64 %0, t; }" : "=r"(a) : "l"(p));
    return a;
}
__device__ __forceinline__ void cp_async16(uint32_t saddr, const void* gptr) {
    asm volatile("cp.async.cg.shared.global [%0], [%1], 16;" :: "r"(saddr), "l"(gptr));
}
#define CP_COMMIT() asm volatile("cp.async.commit_group;" ::: "memory")
#define CP_WAIT(n)  asm volatile("cp.async.wait_group %0;" :: "n"(n) : "memory")

__device__ __forceinline__ void mma_tf32(float* c, const uint32_t* a, const uint32_t* b) {
    asm volatile(
        "mma.sync.aligned.m16n8k8.row.col.f32.tf32.tf32.f32 "
        "{%0,%1,%2,%3}, {%4,%5,%6,%7}, {%8,%9}, {%0,%1,%2,%3};"
        : "+f"(c[0]), "+f"(c[1]), "+f"(c[2]), "+f"(c[3])
        : "r"(a[0]), "r"(a[1]), "r"(a[2]), "r"(a[3]), "r"(b[0]), "r"(b[1]));
}

// ---------------------------------------------------------------------------
// Rope cos/sin table (double-precision source, fp32 table).
// ---------------------------------------------------------------------------
__global__ void rope_table(float* __restrict__ ct, float* __restrict__ st) {
    int idx = blockIdx.x * blockDim.x + threadIdx.x;
    if (idx >= T_ * 64) return;
    int t = idx >> 6, i = idx & 63;
    double w = pow(10000.0, -(double)i / 64.0);
    double ds, dc;
    sincos((double)t * w, &ds, &dc);
    ct[idx] = (float)dc;
    st[idx] = (float)ds;
}

// ---------------------------------------------------------------------------
// prep_x: tf32-RN rounding copy of x.
// ---------------------------------------------------------------------------
__global__ void prep_x(const float* __restrict__ in, float* __restrict__ out, int n4) {
    int i = blockIdx.x * blockDim.x + threadIdx.x;
    if (i >= n4) return;
    float4 v = ((const float4*)in)[i];
    v.x = rna_tf32(v.x); v.y = rna_tf32(v.y); v.z = rna_tf32(v.z); v.w = rna_tf32(v.w);
    ((float4*)out)[i] = v;
}

// ---------------------------------------------------------------------------
// prep_trans: fused transpose+round of all 4 weights. in[K][N] -> out[N][K].
// Flat grid dispatch: Wq 4096 blocks, Wk 1024, Wv 1024, Wo 4096.
// ---------------------------------------------------------------------------
__global__ void prep_trans(const float* __restrict__ wq, const float* __restrict__ wk,
                           const float* __restrict__ wv, const float* __restrict__ wo,
                           float* wqt, float* wkt, float* wvt, float* wot) {
    __shared__ float t[32][33];
    int idx = blockIdx.x;
    const float* in; float* out; int K, N;
    if      (idx < 4096) { in = wq; out = wqt; K = E_;    N = QCOLS; }
    else if (idx < 5120) { in = wk; out = wkt; K = E_;    N = KCOLS; idx -= 4096; }
    else if (idx < 6144) { in = wv; out = wvt; K = E_;    N = KCOLS; idx -= 5120; }
    else                 { in = wo; out = wot; K = QCOLS; N = E_;    idx -= 6144; }
    int nb = N >> 5;
    int kb = idx / nb, jb = idx - kb * nb;
    int k0 = kb * 32, n0 = jb * 32;
    int tx = threadIdx.x, ty = threadIdx.y;
    for (int i = ty; i < 32; i += 8)
        t[i][tx] = in[(size_t)(k0 + i) * N + n0 + tx];
    __syncthreads();
    for (int i = ty; i < 32; i += 8)
        out[(size_t)(n0 + i) * K + k0 + tx] = rna_tf32(t[tx][i]);
}

// ---------------------------------------------------------------------------
// TF32 mma.sync GEMM, B TRANSPOSED [N][K]. 3-way dispatch, 3-stage cp.async,
// 2 CTAs/SM. C[M,N] = A[M,K] @ Bt[N,K]^T. Tile 128x128x32, 256 threads.
// Both A and B smem tiles are [128 rows][32 k] stride 36 -> conflict-free frags.
// mode: 0 plain store, 1 round, 2 rope+scale+round (Q), 3 rope+round (K).
// ---------------------------------------------------------------------------
#define GBM 128
#define GBN 128
#define GBK 32
#define GAST 36
#define GSTAGES 3
#define GA_FLOATS (GBM * GAST)              // 4608
#define GSTAGE_FLOATS (2 * GA_FLOATS)       // 9216
#define GSMEM_BYTES (GSTAGES * GSTAGE_FLOATS * 4)   // 110592

__global__ __launch_bounds__(256, 2) void gemm_mma(
    const float* __restrict__ A,
    const float* __restrict__ B1, float* __restrict__ C1, int mode1, int nblk1, int N1,
    const float* __restrict__ B2, float* __restrict__ C2, int mode2, int nblk2, int N2,
    const float* __restrict__ B3, float* __restrict__ C3, int mode3, int N3,
    int K, const float* __restrict__ ct, const float* __restrict__ st)
{
    extern __shared__ __align__(16) float smem[];
    const int tid = threadIdx.x;
    const int wid = tid >> 5, lane = tid & 31;
    const int warpM = wid & 3, warpN = wid >> 2;
    const int bx = blockIdx.x;

    const float* Bw; float* C; int mode, n0, N;
    if (bx < nblk1)              { Bw = B1; C = C1; mode = mode1; N = N1; n0 = bx * GBN; }
    else if (bx < nblk1 + nblk2) { Bw = B2; C = C2; mode = mode2; N = N2; n0 = (bx - nblk1) * GBN; }
    else                         { Bw = B3; C = C3; mode = mode3; N = N3; n0 = (bx - nblk1 - nblk2) * GBN; }

    const int m0 = blockIdx.y * GBM;
    const int nch = K / GBK;
    const int lr = lane >> 2, lc = lane & 3;

    float acc[2][8][4];
#pragma unroll
    for (int i = 0; i < 2; i++)
#pragma unroll
        for (int j = 0; j < 8; j++)
#pragma unroll
            for (int q = 0; q < 4; q++) acc[i][j][q] = 0.f;

    auto load_chunk = [&](int c, int s) {
        float* As = smem + s * GSTAGE_FLOATS;
        float* Bs = As + GA_FLOATS;
        const uint32_t as_base = smem_u32(As);
        const uint32_t bs_base = smem_u32(Bs);
        // A: 128 rows x 8 chunks of 16B
#pragma unroll
        for (int i = 0; i < 4; i++) {
            int ci = tid + i * 256;
            int row = ci >> 3, ch = ci & 7;
            cp_async16(as_base + (row * GAST + ch * 4) * 4,
                       A + (size_t)(m0 + row) * K + c * GBK + ch * 4);
        }
        // B (transposed [N][K]): 128 n-rows x 8 chunks of 16B — same shape as A
#pragma unroll
        for (int i = 0; i < 4; i++) {
            int ci = tid + i * 256;
            int row = ci >> 3, ch = ci & 7;
            cp_async16(bs_base + (row * GAST + ch * 4) * 4,
                       Bw + (size_t)(n0 + row) * K + c * GBK + ch * 4);
        }
    };

#pragma unroll
    for (int s = 0; s < GSTAGES - 1; s++) { load_chunk(s, s); CP_COMMIT(); }

    for (int c = 0; c < nch; c++) {
        CP_WAIT(GSTAGES - 2);
        __syncthreads();

        int pc = c + GSTAGES - 1;
        if (pc < nch) load_chunk(pc, pc % GSTAGES);
        CP_COMMIT();

        const float* As = smem + (c % GSTAGES) * GSTAGE_FLOATS;
        const float* Bs = As + GA_FLOATS;
        const uint32_t* Asu = (const uint32_t*)As;
        const uint32_t* Bsu = (const uint32_t*)Bs;

#pragma unroll
        for (int kk = 0; kk < 4; kk++) {
            uint32_t afr[2][4], bfr[8][2];
#pragma unroll
            for (int mt = 0; mt < 2; mt++) {
                int row = warpM * 32 + mt * 16 + lr;
                int col = kk * 8 + lc;
                afr[mt][0] = Asu[row * GAST + col];
                afr[mt][1] = Asu[(row + 8) * GAST + col];
                afr[mt][2] = Asu[row * GAST + col + 4];
                afr[mt][3] = Asu[(row + 8) * GAST + col + 4];
            }
#pragma unroll
            for (int nt = 0; nt < 8; nt++) {
                int n = warpN * 64 + nt * 8 + lr;
                int k = kk * 8 + lc;
                bfr[nt][0] = Bsu[n * GAST + k];
                bfr[nt][1] = Bsu[n * GAST + k + 4];
            }
#pragma unroll
            for (int mt = 0; mt < 2; mt++)
#pragma unroll
                for (int nt = 0; nt < 8; nt++)
                    mma_tf32(acc[mt][nt], afr[mt], bfr[nt]);
        }
        __syncthreads();
    }

    // ---- fused epilogue ----
#pragma unroll
    for (int mt = 0; mt < 2; mt++) {
        int rbase = m0 + warpM * 32 + mt * 16 + lr;
#pragma unroll
        for (int nt = 0; nt < 8; nt++) {
            int cbase = n0 + warpN * 64 + nt * 8 + lc * 2;
            float4 v = make_float4(acc[mt][nt][0], acc[mt][nt][1],
                                   acc[mt][nt][2], acc[mt][nt][3]);
            if (mode >= 2) {
                int i  = (cbase & 127) >> 1;
                int t0 = rbase & (T_ - 1);
                int t1 = (rbase + 8) & (T_ - 1);
                float c0 = ct[(t0 << 6) + i], s0 = st[(t0 << 6) + i];
                float c1 = ct[(t1 << 6) + i], s1 = st[(t1 << 6) + i];
                float scale = (mode == 2) ? 0.08838834764831845f : 1.0f;
                float x0 = (v.x * c0 - v.y * s0) * scale;
                float y0 = (v.x * s0 + v.y * c0) * scale;
                float x1 = (v.z * c1 - v.w * s1) * scale;
                float y1 = (v.z * s1 + v.w * c1) * scale;
                v = make_float4(rna_tf32(x0), rna_tf32(y0), rna_tf32(x1), rna_tf32(y1));
            } else if (mode == 1) {
                v.x = rna_tf32(v.x); v.y = rna_tf32(v.y);
                v.z = rna_tf32(v.z); v.w = rna_tf32(v.w);
            }
            *(float2*)(C + (size_t)rbase * N + cbase)       = make_float2(v.x, v.y);
            *(float2*)(C + (size_t)(rbase + 8) * N + cbase) = make_float2(v.z, v.w);
        }
    }
}

// ---------------------------------------------------------------------------
// Causal flash attention with tf32 mma.sync (R6 version: BM=128, 8 warps,
// Q in registers, K/V double-buffered, per-warp P scratch).
// ---------------------------------------------------------------------------
#define FBM 128
#define KST 132
#define VST 136
#define PST 68
#define KS_FLOATS (2 * 64 * KST)
#define VS_FLOATS (2 * 64 * VST)
#define PS_FLOATS (8 * 16 * PST)
#define FA_SMEM_BYTES ((KS_FLOATS + VS_FLOATS + PS_FLOATS) * 4)   // 172032

__global__ __launch_bounds__(256, 1) void flash_mma(const float* __restrict__ Q,
                                                    const float* __restrict__ Km,
                                                    const float* __restrict__ Vm,
                                                    float* __restrict__ ctx) {
    extern __shared__ __align__(16) float sm[];
    float* KsB = sm;
    float* VsB = sm + KS_FLOATS;
    float* PsB = VsB + VS_FLOATS;

    const int tid = threadIdx.x;
    const int wid = tid >> 5, lane = tid & 31;
    const int lr = lane >> 2, lc = lane & 3;
    const int m0 = (int)(gridDim.x - 1 - blockIdx.x) * FBM;
    const int h = blockIdx.y, b = blockIdx.z;
    const int kvh = h >> 2;

    float* Psw = PsB + wid * 16 * PST;
    uint32_t* Psu = (uint32_t*)Psw;

    uint32_t qa[16][4];
    {
        const float* qsrc = Q + (size_t)(b * T_ + m0 + wid * 16) * QCOLS + h * 128;
#pragma unroll
        for (int hh = 0; hh < 2; hh++) {
#pragma unroll
            for (int i = 0; i < 8; i++) {
                int task = lane + i * 32;
                int row = task >> 4, c4 = task & 15;
                float4 v = *(const float4*)(qsrc + (size_t)row * QCOLS + hh * 64 + c4 * 4);
                *(float4*)&Psw[row * PST + c4 * 4] = v;
            }
            __syncwarp();
#pragma unroll
            for (int k8 = 0; k8 < 8; k8++) {
                int kk = hh * 8 + k8;
                qa[kk][0] = Psu[lr * PST + k8 * 8 + lc];
                qa[kk][1] = Psu[(lr + 8) * PST + k8 * 8 + lc];
                qa[kk][2] = Psu[lr * PST + k8 * 8 + lc + 4];
                qa[kk][3] = Psu[(lr + 8) * PST + k8 * 8 + lc + 4];
            }
            __syncwarp();
        }
    }

    float oacc[16][4];
#pragma unroll
    for (int i = 0; i < 16; i++)
#pragma unroll
        for (int q = 0; q < 4; q++) oacc[i][q] = 0.f;
    float m_i[2] = {-1e30f, -1e30f};
    float l_i[2] = {0.f, 0.f};

    const int ntiles = m0 / 64 + 2;

    auto load_kv = [&](int t, int stg) {
        const float* kb = Km + (size_t)(b * T_ + t * 64) * KCOLS + kvh * 128;
        const float* vb = Vm + (size_t)(b * T_ + t * 64) * KCOLS + kvh * 128;
        uint32_t ka = smem_u32(KsB + stg * 64 * KST);
        uint32_t va = smem_u32(VsB + stg * 64 * VST);
#pragma unroll
        for (int i = 0; i < 8; i++) {
            int task = tid + i * 256;
            int row = task >> 5, ch = task & 31;
            cp_async16(ka + (row * KST + ch * 4) * 4, kb + (size_t)row * KCOLS + ch * 4);
        }
#pragma unroll
        for (int i = 0; i < 8; i++) {
            int task = tid + i * 256;
            int row = task >> 5, ch = task & 31;
            cp_async16(va + (row * VST + ch * 4) * 4, vb + (size_t)row * KCOLS + ch * 4);
        }
    };

    load_kv(0, 0);
    CP_COMMIT();

    for (int t = 0; t < ntiles; t++) {
        if (t + 1 < ntiles) { load_kv(t + 1, (t + 1) & 1); CP_COMMIT(); CP_WAIT(1); }
        else                { CP_WAIT(0); }
        __syncthreads();

        const uint32_t* Ksu = (const uint32_t*)(KsB + (t & 1) * 64 * KST);
        const uint32_t* Vsu = (const uint32_t*)(VsB + (t & 1) * 64 * VST);

        float sacc[8][4];
#pragma unroll
        for (int nt = 0; nt < 8; nt++)
#pragma unroll
            for (int q = 0; q < 4; q++) sacc[nt][q] = 0.f;

#pragma unroll
        for (int kk = 0; kk < 16; kk++) {
            uint32_t bfr[8][2];
#pragma unroll
            for (int nt = 0; nt < 8; nt++) {
                bfr[nt][0] = Ksu[(nt * 8 + lr) * KST + kk * 8 + lc];
                bfr[nt][1] = Ksu[(nt * 8 + lr) * KST + kk * 8 + lc + 4];
            }
#pragma unroll
            for (int nt = 0; nt < 8; nt++)
                mma_tf32(sacc[nt], qa[kk], bfr[nt]);
        }

        const int row0g = m0 + wid * 16 + lr;
        const int row1g = row0g + 8;
        if (t * 64 + 63 > m0 + wid * 16) {
#pragma unroll
            for (int nt = 0; nt < 8; nt++) {
                int colg = t * 64 + nt * 8 + 2 * lc;
                if (colg     > row0g) sacc[nt][0] = -1e30f;
                if (colg + 1 > row0g) sacc[nt][1] = -1e30f;
                if (colg     > row1g) sacc[nt][2] = -1e30f;
                if (colg + 1 > row1g) sacc[nt][3] = -1e30f;
            }
        }

        float rmax0 = -1e30f, rmax1 = -1e30f;
#pragma unroll
        for (int nt = 0; nt < 8; nt++) {
            rmax0 = fmaxf(rmax0, fmaxf(sacc[nt][0], sacc[nt][1]));
            rmax1 = fmaxf(rmax1, fmaxf(sacc[nt][2], sacc[nt][3]));
        }
        rmax0 = fmaxf(rmax0, __shfl_xor_sync(0xffffffffu, rmax0, 1));
        rmax0 = fmaxf(rmax0, __shfl_xor_sync(0xffffffffu, rmax0, 2));
        rmax1 = fmaxf(rmax1, __shfl_xor_sync(0xffffffffu, rmax1, 1));
        rmax1 = fmaxf(rmax1, __shfl_xor_sync(0xffffffffu, rmax1, 2));

        float mnew0 = fmaxf(m_i[0], rmax0);
        float mnew1 = fmaxf(m_i[1], rmax1);
        float alpha0 = __expf(m_i[0] - mnew0);
        float alpha1 = __expf(m_i[1] - mnew1);

        float rsum0 = 0.f, rsum1 = 0.f;
#pragma unroll
        for (int nt = 0; nt < 8; nt++) {
            float p0 = rna_tf32(__expf(sacc[nt][0] - mnew0));
            float p1 = rna_tf32(__expf(sacc[nt][1] - mnew0));
            float p2 = rna_tf32(__expf(sacc[nt][2] - mnew1));
            float p3 = rna_tf32(__expf(sacc[nt][3] - mnew1));
            rsum0 += p0 + p1;
            rsum1 += p2 + p3;
            *(float2*)&Psw[lr * PST + nt * 8 + 2 * lc]       = make_float2(p0, p1);
            *(float2*)&Psw[(lr + 8) * PST + nt * 8 + 2 * lc] = make_float2(p2, p3);
        }
        rsum0 += __shfl_xor_sync(0xffffffffu, rsum0, 1);
        rsum0 += __shfl_xor_sync(0xffffffffu, rsum0, 2);
        rsum1 += __shfl_xor_sync(0xffffffffu, rsum1, 1);
        rsum1 += __shfl_xor_sync(0xffffffffu, rsum1, 2);

        l_i[0] = l_i[0] * alpha0 + rsum0;
        l_i[1] = l_i[1] * alpha1 + rsum1;
        m_i[0] = mnew0;
        m_i[1] = mnew1;
#pragma unroll
        for (int nt = 0; nt < 16; nt++) {
            oacc[nt][0] *= alpha0; oacc[nt][1] *= alpha0;
            oacc[nt][2] *= alpha1; oacc[nt][3] *= alpha1;
        }
        __syncwarp();

#pragma unroll
        for (int kk = 0; kk < 8; kk++) {
            uint32_t pa[4];
            pa[0] = Psu[lr * PST + kk * 8 + lc];
            pa[1] = Psu[(lr + 8) * PST + kk * 8 + lc];
            pa[2] = Psu[lr * PST + kk * 8 + lc + 4];
            pa[3] = Psu[(lr + 8) * PST + kk * 8 + lc + 4];
#pragma unroll
            for (int nt = 0; nt < 16; nt++) {
                uint32_t bfr[2];
                bfr[0] = Vsu[(kk * 8 + lc) * VST + nt * 8 + lr];
                bfr[1] = Vsu[(kk * 8 + lc + 4) * VST + nt * 8 + lr];
                mma_tf32(oacc[nt], pa, bfr);
            }
        }
        __syncwarp();
        __syncthreads();
    }

    float inv0 = 1.0f / l_i[0];
    float inv1 = 1.0f / l_i[1];
    const int row0g = m0 + wid * 16 + lr;
    float* c0 = ctx + (size_t)(b * T_ + row0g) * QCOLS + h * 128;
    float* c1 = ctx + (size_t)(b * T_ + row0g + 8) * QCOLS + h * 128;
#pragma unroll
    for (int nt = 0; nt < 16; nt++) {
        int col = nt * 8 + 2 * lc;
        *(float2*)(c0 + col) = make_float2(rna_tf32(oacc[nt][0] * inv0),
                                           rna_tf32(oacc[nt][1] * inv0));
        *(float2*)(c1 + col) = make_float2(rna_tf32(oacc[nt][2] * inv1),
                                           rna_tf32(oacc[nt][3] * inv1));
    }
}

// ---------------------------------------------------------------------------
// Host
// ---------------------------------------------------------------------------
extern "C" void kernel_launch(void* const* d_in, const int* in_sizes, int n_in,
                              void* d_out, int out_size) {
    const float* x    = (const float*)d_in[0];
    const float* Wq   = (const float*)d_in[1];
    const float* Wk   = (const float*)d_in[2];
    const float* Wv   = (const float*)d_in[3];
    const float* Wout = (const float*)d_in[4];
    float* out = (float*)d_out;

    float *xr, *WqT, *WkT, *WvT, *WoT, *Qb, *Kb, *Vb, *Cb, *ctab, *stab;
    cudaGetSymbolAddress((void**)&xr,  g_xr);
    cudaGetSymbolAddress((void**)&WqT, g_WqT);
    cudaGetSymbolAddress((void**)&WkT, g_WkT);
    cudaGetSymbolAddress((void**)&WvT, g_WvT);
    cudaGetSymbolAddress((void**)&WoT, g_WoT);
    cudaGetSymbolAddress((void**)&Qb,  g_Q);
    cudaGetSymbolAddress((void**)&Kb,  g_K);
    cudaGetSymbolAddress((void**)&Vb,  g_V);
    cudaGetSymbolAddress((void**)&Cb,  g_ctx);
    cudaGetSymbolAddress((void**)&ctab, g_rcos);
    cudaGetSymbolAddress((void**)&stab, g_rsin);

    cudaFuncSetAttribute(gemm_mma, cudaFuncAttributeMaxDynamicSharedMemorySize, GSMEM_BYTES);
    cudaFuncSetAttribute(flash_mma, cudaFuncAttributeMaxDynamicSharedMemorySize, FA_SMEM_BYTES);

    // 1) prep: round x; transpose+round all weights
    prep_x<<<(ROWS * E_ / 4 + 255) / 256, 256>>>(x, xr, ROWS * E_ / 4);
    prep_trans<<<10240, dim3(32, 8)>>>(Wq, Wk, Wv, Wout, WqT, WkT, WvT, WoT);

    // 2) rope table
    rope_table<<<(T_ * 64 + 255) / 256, 256>>>(ctab, stab);

    // 3) Q + K + V projections in ONE launch
    gemm_mma<<<dim3(24, ROWS / GBM), 256, GSMEM_BYTES>>>(
        xr,
        WqT, Qb, 2, QCOLS / GBN, QCOLS,
        WkT, Kb, 3, KCOLS / GBN, KCOLS,
        WvT, Vb, 1, KCOLS,
        E_, ctab, stab);

    // 4) attention
    flash_mma<<<dim3(T_ / FBM, H_, B_), 256, FA_SMEM_BYTES>>>(Qb, Kb, Vb, Cb);

    // 5) output projection
    gemm_mma<<<dim3(E_ / GBN, ROWS / GBM), 256, GSMEM_BYTES>>>(
        Cb,
        WoT, out, 0, E_ / GBN, E_,
        WoT, out, 0, 0, E_,
        WoT, out, 0, E_,
        QCOLS, ctab, stab);
}

// round 9
// speedup vs baseline: 1.0964x; 1.0101x over previous
#include <cuda_runtime.h>
#include <cuda_bf16.h>
#include <math.h>
#include <stdint.h>

// Problem constants
#define B_   2
#define T_   2048
#define E_   2048
#define H_   16
#define HKV_ 4
#define D_   128
#define ROWS (B_ * T_)          // 4096
#define QCOLS (H_ * D_)         // 2048
#define KCOLS (HKV_ * D_)       // 512

// ---------------------------------------------------------------------------
// Scratch (allocation-free: device globals). Weights stored TRANSPOSED [N][K].
// ---------------------------------------------------------------------------
__device__ __align__(1024) float g_xr [(size_t)ROWS * E_];
__device__ __align__(1024) float g_WqT[(size_t)QCOLS * E_];
__device__ __align__(1024) float g_WkT[(size_t)KCOLS * E_];
__device__ __align__(1024) float g_WvT[(size_t)KCOLS * E_];
__device__ __align__(1024) float g_WoT[(size_t)E_ * QCOLS];
__device__ __align__(1024) float g_Q  [(size_t)ROWS * QCOLS];
__device__ __align__(1024) float g_K  [(size_t)ROWS * KCOLS];
__device__ __align__(1024) float g_V  [(size_t)ROWS * KCOLS];
__device__ __align__(1024) float g_ctx[(size_t)ROWS * QCOLS];
__device__ __align__(1024) float g_rcos[T_ * 64];
__device__ __align__(1024) float g_rsin[T_ * 64];

// ---------------------------------------------------------------------------
// Helpers
// ---------------------------------------------------------------------------
__device__ __forceinline__ float rna_tf32(float x) {
    uint32_t y;
    asm("cvt.rna.tf32.f32 %0, %1;" : "=r"(y) : "f"(x));
    return __uint_as_float(y);
}
__device__ __forceinline__ uint32_t smem_u32(const void* p) {
    uint32_t a;
    asm("{ .reg .u64 t; cvta.to.shared.u64 t, %1; cvt.u32.u64 %0, t; }" : "=r"(a) : "l"(p));
    return a;
}
__device__ __forceinline__ void cp_async16(uint32_t saddr, const void* gptr) {
    asm volatile("cp.async.cg.shared.global [%0], [%1], 16;" :: "r"(saddr), "l"(gptr));
}
#define CP_COMMIT() asm volatile("cp.async.commit_group;" ::: "memory")
#define CP_WAIT(n)  asm volatile("cp.async.wait_group %0;" :: "n"(n) : "memory")

__device__ __forceinline__ void mma_tf32(float* c, const uint32_t* a, const uint32_t* b) {
    asm volatile(
        "mma.sync.aligned.m16n8k8.row.col.f32.tf32.tf32.f32 "
        "{%0,%1,%2,%3}, {%4,%5,%6,%7}, {%8,%9}, {%0,%1,%2,%3};"
        : "+f"(c[0]), "+f"(c[1]), "+f"(c[2]), "+f"(c[3])
        : "r"(a[0]), "r"(a[1]), "r"(a[2]), "r"(a[3]), "r"(b[0]), "r"(b[1]));
}

// ---------------------------------------------------------------------------
// Rope cos/sin table (double-precision source, fp32 table).
// ---------------------------------------------------------------------------
__global__ void rope_table(float* __restrict__ ct, float* __restrict__ st) {
    int idx = blockIdx.x * blockDim.x + threadIdx.x;
    if (idx >= T_ * 64) return;
    int t = idx >> 6, i = idx & 63;
    double w = pow(10000.0, -(double)i / 64.0);
    double ds, dc;
    sincos((double)t * w, &ds, &dc);
    ct[idx] = (float)dc;
    st[idx] = (float)ds;
}

// ---------------------------------------------------------------------------
// prep_x: tf32-RN rounding copy of x.
// ---------------------------------------------------------------------------
__global__ void prep_x(const float* __restrict__ in, float* __restrict__ out, int n4) {
    int i = blockIdx.x * blockDim.x + threadIdx.x;
    if (i >= n4) return;
    float4 v = ((const float4*)in)[i];
    v.x = rna_tf32(v.x); v.y = rna_tf32(v.y); v.z = rna_tf32(v.z); v.w = rna_tf32(v.w);
    ((float4*)out)[i] = v;
}

// ---------------------------------------------------------------------------
// prep_trans: fused transpose+round of all 4 weights. in[K][N] -> out[N][K].
// ---------------------------------------------------------------------------
__global__ void prep_trans(const float* __restrict__ wq, const float* __restrict__ wk,
                           const float* __restrict__ wv, const float* __restrict__ wo,
                           float* wqt, float* wkt, float* wvt, float* wot) {
    __shared__ float t[32][33];
    int idx = blockIdx.x;
    const float* in; float* out; int K, N;
    if      (idx < 4096) { in = wq; out = wqt; K = E_;    N = QCOLS; }
    else if (idx < 5120) { in = wk; out = wkt; K = E_;    N = KCOLS; idx -= 4096; }
    else if (idx < 6144) { in = wv; out = wvt; K = E_;    N = KCOLS; idx -= 5120; }
    else                 { in = wo; out = wot; K = QCOLS; N = E_;    idx -= 6144; }
    int nb = N >> 5;
    int kb = idx / nb, jb = idx - kb * nb;
    int k0 = kb * 32, n0 = jb * 32;
    int tx = threadIdx.x, ty = threadIdx.y;
    for (int i = ty; i < 32; i += 8)
        t[i][tx] = in[(size_t)(k0 + i) * N + n0 + tx];
    __syncthreads();
    for (int i = ty; i < 32; i += 8)
        out[(size_t)(n0 + i) * K + k0 + tx] = rna_tf32(t[tx][i]);
}

// ---------------------------------------------------------------------------
// TF32 mma.sync GEMM, B TRANSPOSED [N][K]. CTA tile 128x256x32, 8 warps in
// 2(m) x 4(n), warp tile 64x64 (32 accumulator tiles -> deep ILP).
// 3-stage cp.async, ONE barrier per chunk. 1 CTA/SM, full register budget.
// mode: 0 plain store, 1 round, 2 rope+scale+round (Q), 3 rope+round (K).
// ---------------------------------------------------------------------------
#define GBM 128
#define GBN 256
#define GBK 32
#define GAST 36
#define GSTAGES 3
#define GA_FLOATS (GBM * GAST)              // 4608
#define GB_FLOATS (GBN * GAST)              // 9216
#define GSTAGE_FLOATS (GA_FLOATS + GB_FLOATS)   // 13824
#define GSMEM_BYTES (GSTAGES * GSTAGE_FLOATS * 4)   // 165888

__global__ __launch_bounds__(256, 1) void gemm_mma(
    const float* __restrict__ A,
    const float* __restrict__ B1, float* __restrict__ C1, int mode1, int nblk1, int N1,
    const float* __restrict__ B2, float* __restrict__ C2, int mode2, int nblk2, int N2,
    const float* __restrict__ B3, float* __restrict__ C3, int mode3, int N3,
    int K, const float* __restrict__ ct, const float* __restrict__ st)
{
    extern __shared__ __align__(16) float smem[];
    const int tid = threadIdx.x;
    const int wid = tid >> 5, lane = tid & 31;
    const int warpM = wid & 1, warpN = wid >> 1;   // 2 x 4
    const int bx = blockIdx.x;

    const float* Bw; float* C; int mode, n0, N;
    if (bx < nblk1)              { Bw = B1; C = C1; mode = mode1; N = N1; n0 = bx * GBN; }
    else if (bx < nblk1 + nblk2) { Bw = B2; C = C2; mode = mode2; N = N2; n0 = (bx - nblk1) * GBN; }
    else                         { Bw = B3; C = C3; mode = mode3; N = N3; n0 = (bx - nblk1 - nblk2) * GBN; }

    const int m0 = blockIdx.y * GBM;
    const int nch = K / GBK;
    const int lr = lane >> 2, lc = lane & 3;

    float acc[4][8][4];
#pragma unroll
    for (int i = 0; i < 4; i++)
#pragma unroll
        for (int j = 0; j < 8; j++)
#pragma unroll
            for (int q = 0; q < 4; q++) acc[i][j][q] = 0.f;

    auto load_chunk = [&](int c, int s) {
        float* As = smem + s * GSTAGE_FLOATS;
        float* Bs = As + GA_FLOATS;
        const uint32_t as_base = smem_u32(As);
        const uint32_t bs_base = smem_u32(Bs);
        // A: 128 rows x 8 chunks of 16B = 1024 tasks
#pragma unroll
        for (int i = 0; i < 4; i++) {
            int ci = tid + i * 256;
            int row = ci >> 3, ch = ci & 7;
            cp_async16(as_base + (row * GAST + ch * 4) * 4,
                       A + (size_t)(m0 + row) * K + c * GBK + ch * 4);
        }
        // B ([N][K]): 256 n-rows x 8 chunks of 16B = 2048 tasks
#pragma unroll
        for (int i = 0; i < 8; i++) {
            int ci = tid + i * 256;
            int row = ci >> 3, ch = ci & 7;
            cp_async16(bs_base + (row * GAST + ch * 4) * 4,
                       Bw + (size_t)(n0 + row) * K + c * GBK + ch * 4);
        }
    };

#pragma unroll
    for (int s = 0; s < GSTAGES - 1; s++) { load_chunk(s, s); CP_COMMIT(); }

    for (int c = 0; c < nch; c++) {
        CP_WAIT(GSTAGES - 2);
        __syncthreads();   // sole barrier: data arrival + stage-reuse safety

        int pc = c + GSTAGES - 1;
        if (pc < nch) load_chunk(pc, pc % GSTAGES);
        CP_COMMIT();

        const float* As = smem + (c % GSTAGES) * GSTAGE_FLOATS;
        const float* Bs = As + GA_FLOATS;
        const uint32_t* Asu = (const uint32_t*)As;
        const uint32_t* Bsu = (const uint32_t*)Bs;

#pragma unroll
        for (int kk = 0; kk < 4; kk++) {
            uint32_t afr[4][4], bfr[8][2];
#pragma unroll
            for (int mt = 0; mt < 4; mt++) {
                int row = warpM * 64 + mt * 16 + lr;
                int col = kk * 8 + lc;
                afr[mt][0] = Asu[row * GAST + col];
                afr[mt][1] = Asu[(row + 8) * GAST + col];
                afr[mt][2] = Asu[row * GAST + col + 4];
                afr[mt][3] = Asu[(row + 8) * GAST + col + 4];
            }
#pragma unroll
            for (int nt = 0; nt < 8; nt++) {
                int n = warpN * 64 + nt * 8 + lr;
                int k = kk * 8 + lc;
                bfr[nt][0] = Bsu[n * GAST + k];
                bfr[nt][1] = Bsu[n * GAST + k + 4];
            }
#pragma unroll
            for (int mt = 0; mt < 4; mt++)
#pragma unroll
                for (int nt = 0; nt < 8; nt++)
                    mma_tf32(acc[mt][nt], afr[mt], bfr[nt]);
        }
    }

    // ---- fused epilogue ----
#pragma unroll
    for (int mt = 0; mt < 4; mt++) {
        int rbase = m0 + warpM * 64 + mt * 16 + lr;
#pragma unroll
        for (int nt = 0; nt < 8; nt++) {
            int cbase = n0 + warpN * 64 + nt * 8 + lc * 2;
            float4 v = make_float4(acc[mt][nt][0], acc[mt][nt][1],
                                   acc[mt][nt][2], acc[mt][nt][3]);
            if (mode >= 2) {
                int i  = (cbase & 127) >> 1;
                int t0 = rbase & (T_ - 1);
                int t1 = (rbase + 8) & (T_ - 1);
                float c0 = ct[(t0 << 6) + i], s0 = st[(t0 << 6) + i];
                float c1 = ct[(t1 << 6) + i], s1 = st[(t1 << 6) + i];
                float scale = (mode == 2) ? 0.08838834764831845f : 1.0f;
                float x0 = (v.x * c0 - v.y * s0) * scale;
                float y0 = (v.x * s0 + v.y * c0) * scale;
                float x1 = (v.z * c1 - v.w * s1) * scale;
                float y1 = (v.z * s1 + v.w * c1) * scale;
                v = make_float4(rna_tf32(x0), rna_tf32(y0), rna_tf32(x1), rna_tf32(y1));
            } else if (mode == 1) {
                v.x = rna_tf32(v.x); v.y = rna_tf32(v.y);
                v.z = rna_tf32(v.z); v.w = rna_tf32(v.w);
            }
            *(float2*)(C + (size_t)rbase * N + cbase)       = make_float2(v.x, v.y);
            *(float2*)(C + (size_t)(rbase + 8) * N + cbase) = make_float2(v.z, v.w);
        }
    }
}

// ---------------------------------------------------------------------------
// Causal flash attention with tf32 mma.sync (R6 version, unchanged).
// ---------------------------------------------------------------------------
#define FBM 128
#define KST 132
#define VST 136
#define PST 68
#define KS_FLOATS (2 * 64 * KST)
#define VS_FLOATS (2 * 64 * VST)
#define PS_FLOATS (8 * 16 * PST)
#define FA_SMEM_BYTES ((KS_FLOATS + VS_FLOATS + PS_FLOATS) * 4)   // 172032

__global__ __launch_bounds__(256, 1) void flash_mma(const float* __restrict__ Q,
                                                    const float* __restrict__ Km,
                                                    const float* __restrict__ Vm,
                                                    float* __restrict__ ctx) {
    extern __shared__ __align__(16) float sm[];
    float* KsB = sm;
    float* VsB = sm + KS_FLOATS;
    float* PsB = VsB + VS_FLOATS;

    const int tid = threadIdx.x;
    const int wid = tid >> 5, lane = tid & 31;
    const int lr = lane >> 2, lc = lane & 3;
    const int m0 = (int)(gridDim.x - 1 - blockIdx.x) * FBM;
    const int h = blockIdx.y, b = blockIdx.z;
    const int kvh = h >> 2;

    float* Psw = PsB + wid * 16 * PST;
    uint32_t* Psu = (uint32_t*)Psw;

    uint32_t qa[16][4];
    {
        const float* qsrc = Q + (size_t)(b * T_ + m0 + wid * 16) * QCOLS + h * 128;
#pragma unroll
        for (int hh = 0; hh < 2; hh++) {
#pragma unroll
            for (int i = 0; i < 8; i++) {
                int task = lane + i * 32;
                int row = task >> 4, c4 = task & 15;
                float4 v = *(const float4*)(qsrc + (size_t)row * QCOLS + hh * 64 + c4 * 4);
                *(float4*)&Psw[row * PST + c4 * 4] = v;
            }
            __syncwarp();
#pragma unroll
            for (int k8 = 0; k8 < 8; k8++) {
                int kk = hh * 8 + k8;
                qa[kk][0] = Psu[lr * PST + k8 * 8 + lc];
                qa[kk][1] = Psu[(lr + 8) * PST + k8 * 8 + lc];
                qa[kk][2] = Psu[lr * PST + k8 * 8 + lc + 4];
                qa[kk][3] = Psu[(lr + 8) * PST + k8 * 8 + lc + 4];
            }
            __syncwarp();
        }
    }

    float oacc[16][4];
#pragma unroll
    for (int i = 0; i < 16; i++)
#pragma unroll
        for (int q = 0; q < 4; q++) oacc[i][q] = 0.f;
    float m_i[2] = {-1e30f, -1e30f};
    float l_i[2] = {0.f, 0.f};

    const int ntiles = m0 / 64 + 2;

    auto load_kv = [&](int t, int stg) {
        const float* kb = Km + (size_t)(b * T_ + t * 64) * KCOLS + kvh * 128;
        const float* vb = Vm + (size_t)(b * T_ + t * 64) * KCOLS + kvh * 128;
        uint32_t ka = smem_u32(KsB + stg * 64 * KST);
        uint32_t va = smem_u32(VsB + stg * 64 * VST);
#pragma unroll
        for (int i = 0; i < 8; i++) {
            int task = tid + i * 256;
            int row = task >> 5, ch = task & 31;
            cp_async16(ka + (row * KST + ch * 4) * 4, kb + (size_t)row * KCOLS + ch * 4);
        }
#pragma unroll
        for (int i = 0; i < 8; i++) {
            int task = tid + i * 256;
            int row = task >> 5, ch = task & 31;
            cp_async16(va + (row * VST + ch * 4) * 4, vb + (size_t)row * KCOLS + ch * 4);
        }
    };

    load_kv(0, 0);
    CP_COMMIT();

    for (int t = 0; t < ntiles; t++) {
        if (t + 1 < ntiles) { load_kv(t + 1, (t + 1) & 1); CP_COMMIT(); CP_WAIT(1); }
        else                { CP_WAIT(0); }
        __syncthreads();

        const uint32_t* Ksu = (const uint32_t*)(KsB + (t & 1) * 64 * KST);
        const uint32_t* Vsu = (const uint32_t*)(VsB + (t & 1) * 64 * VST);

        float sacc[8][4];
#pragma unroll
        for (int nt = 0; nt < 8; nt++)
#pragma unroll
            for (int q = 0; q < 4; q++) sacc[nt][q] = 0.f;

#pragma unroll
        for (int kk = 0; kk < 16; kk++) {
            uint32_t bfr[8][2];
#pragma unroll
            for (int nt = 0; nt < 8; nt++) {
                bfr[nt][0] = Ksu[(nt * 8 + lr) * KST + kk * 8 + lc];
                bfr[nt][1] = Ksu[(nt * 8 + lr) * KST + kk * 8 + lc + 4];
            }
#pragma unroll
            for (int nt = 0; nt < 8; nt++)
                mma_tf32(sacc[nt], qa[kk], bfr[nt]);
        }

        const int row0g = m0 + wid * 16 + lr;
        const int row1g = row0g + 8;
        if (t * 64 + 63 > m0 + wid * 16) {
#pragma unroll
            for (int nt = 0; nt < 8; nt++) {
                int colg = t * 64 + nt * 8 + 2 * lc;
                if (colg     > row0g) sacc[nt][0] = -1e30f;
                if (colg + 1 > row0g) sacc[nt][1] = -1e30f;
                if (colg     > row1g) sacc[nt][2] = -1e30f;
                if (colg + 1 > row1g) sacc[nt][3] = -1e30f;
            }
        }

        float rmax0 = -1e30f, rmax1 = -1e30f;
#pragma unroll
        for (int nt = 0; nt < 8; nt++) {
            rmax0 = fmaxf(rmax0, fmaxf(sacc[nt][0], sacc[nt][1]));
            rmax1 = fmaxf(rmax1, fmaxf(sacc[nt][2], sacc[nt][3]));
        }
        rmax0 = fmaxf(rmax0, __shfl_xor_sync(0xffffffffu, rmax0, 1));
        rmax0 = fmaxf(rmax0, __shfl_xor_sync(0xffffffffu, rmax0, 2));
        rmax1 = fmaxf(rmax1, __shfl_xor_sync(0xffffffffu, rmax1, 1));
        rmax1 = fmaxf(rmax1, __shfl_xor_sync(0xffffffffu, rmax1, 2));

        float mnew0 = fmaxf(m_i[0], rmax0);
        float mnew1 = fmaxf(m_i[1], rmax1);
        float alpha0 = __expf(m_i[0] - mnew0);
        float alpha1 = __expf(m_i[1] - mnew1);

        float rsum0 = 0.f, rsum1 = 0.f;
#pragma unroll
        for (int nt = 0; nt < 8; nt++) {
            float p0 = rna_tf32(__expf(sacc[nt][0] - mnew0));
            float p1 = rna_tf32(__expf(sacc[nt][1] - mnew0));
            float p2 = rna_tf32(__expf(sacc[nt][2] - mnew1));
            float p3 = rna_tf32(__expf(sacc[nt][3] - mnew1));
            rsum0 += p0 + p1;
            rsum1 += p2 + p3;
            *(float2*)&Psw[lr * PST + nt * 8 + 2 * lc]       = make_float2(p0, p1);
            *(float2*)&Psw[(lr + 8) * PST + nt * 8 + 2 * lc] = make_float2(p2, p3);
        }
        rsum0 += __shfl_xor_sync(0xffffffffu, rsum0, 1);
        rsum0 += __shfl_xor_sync(0xffffffffu, rsum0, 2);
        rsum1 += __shfl_xor_sync(0xffffffffu, rsum1, 1);
        rsum1 += __shfl_xor_sync(0xffffffffu, rsum1, 2);

        l_i[0] = l_i[0] * alpha0 + rsum0;
        l_i[1] = l_i[1] * alpha1 + rsum1;
        m_i[0] = mnew0;
        m_i[1] = mnew1;
#pragma unroll
        for (int nt = 0; nt < 16; nt++) {
            oacc[nt][0] *= alpha0; oacc[nt][1] *= alpha0;
            oacc[nt][2] *= alpha1; oacc[nt][3] *= alpha1;
        }
        __syncwarp();

#pragma unroll
        for (int kk = 0; kk < 8; kk++) {
            uint32_t pa[4];
            pa[0] = Psu[lr * PST + kk * 8 + lc];
            pa[1] = Psu[(lr + 8) * PST + kk * 8 + lc];
            pa[2] = Psu[lr * PST + kk * 8 + lc + 4];
            pa[3] = Psu[(lr + 8) * PST + kk * 8 + lc + 4];
#pragma unroll
            for (int nt = 0; nt < 16; nt++) {
                uint32_t bfr[2];
                bfr[0] = Vsu[(kk * 8 + lc) * VST + nt * 8 + lr];
                bfr[1] = Vsu[(kk * 8 + lc + 4) * VST + nt * 8 + lr];
                mma_tf32(oacc[nt], pa, bfr);
            }
        }
        __syncwarp();
        __syncthreads();
    }

    float inv0 = 1.0f / l_i[0];
    float inv1 = 1.0f / l_i[1];
    const int row0g = m0 + wid * 16 + lr;
    float* c0 = ctx + (size_t)(b * T_ + row0g) * QCOLS + h * 128;
    float* c1 = ctx + (size_t)(b * T_ + row0g + 8) * QCOLS + h * 128;
#pragma unroll
    for (int nt = 0; nt < 16; nt++) {
        int col = nt * 8 + 2 * lc;
        *(float2*)(c0 + col) = make_float2(rna_tf32(oacc[nt][0] * inv0),
                                           rna_tf32(oacc[nt][1] * inv0));
        *(float2*)(c1 + col) = make_float2(rna_tf32(oacc[nt][2] * inv1),
                                           rna_tf32(oacc[nt][3] * inv1));
    }
}

// ---------------------------------------------------------------------------
// Host
// ---------------------------------------------------------------------------
extern "C" void kernel_launch(void* const* d_in, const int* in_sizes, int n_in,
                              void* d_out, int out_size) {
    const float* x    = (const float*)d_in[0];
    const float* Wq   = (const float*)d_in[1];
    const float* Wk   = (const float*)d_in[2];
    const float* Wv   = (const float*)d_in[3];
    const float* Wout = (const float*)d_in[4];
    float* out = (float*)d_out;

    float *xr, *WqT, *WkT, *WvT, *WoT, *Qb, *Kb, *Vb, *Cb, *ctab, *stab;
    cudaGetSymbolAddress((void**)&xr,  g_xr);
    cudaGetSymbolAddress((void**)&WqT, g_WqT);
    cudaGetSymbolAddress((void**)&WkT, g_WkT);
    cudaGetSymbolAddress((void**)&WvT, g_WvT);
    cudaGetSymbolAddress((void**)&WoT, g_WoT);
    cudaGetSymbolAddress((void**)&Qb,  g_Q);
    cudaGetSymbolAddress((void**)&Kb,  g_K);
    cudaGetSymbolAddress((void**)&Vb,  g_V);
    cudaGetSymbolAddress((void**)&Cb,  g_ctx);
    cudaGetSymbolAddress((void**)&ctab, g_rcos);
    cudaGetSymbolAddress((void**)&stab, g_rsin);

    cudaFuncSetAttribute(gemm_mma, cudaFuncAttributeMaxDynamicSharedMemorySize, GSMEM_BYTES);
    cudaFuncSetAttribute(flash_mma, cudaFuncAttributeMaxDynamicSharedMemorySize, FA_SMEM_BYTES);

    // 1) prep: round x; transpose+round all weights
    prep_x<<<(ROWS * E_ / 4 + 255) / 256, 256>>>(x, xr, ROWS * E_ / 4);
    prep_trans<<<10240, dim3(32, 8)>>>(Wq, Wk, Wv, Wout, WqT, WkT, WvT, WoT);

    // 2) rope table
    rope_table<<<(T_ * 64 + 255) / 256, 256>>>(ctab, stab);

    // 3) Q + K + V projections in ONE launch (grid.x = 8 + 2 + 2 = 12)
    gemm_mma<<<dim3(12, ROWS / GBM), 256, GSMEM_BYTES>>>(
        xr,
        WqT, Qb, 2, QCOLS / GBN, QCOLS,
        WkT, Kb, 3, KCOLS / GBN, KCOLS,
        WvT, Vb, 1, KCOLS,
        E_, ctab, stab);

    // 4) attention
    flash_mma<<<dim3(T_ / FBM, H_, B_), 256, FA_SMEM_BYTES>>>(Qb, Kb, Vb, Cb);

    // 5) output projection (grid.x = 2048/256 = 8)
    gemm_mma<<<dim3(E_ / GBN, ROWS / GBM), 256, GSMEM_BYTES>>>(
        Cb,
        WoT, out, 0, E_ / GBN, E_,
        WoT, out, 0, 0, E_,
        WoT, out, 0, E_,
        QCOLS, ctab, stab);
}

// round 11
// speedup vs baseline: 1.7775x; 1.6212x over previous
#include <cuda_runtime.h>
#include <cuda_fp16.h>
#include <math.h>
#include <stdint.h>

// Problem constants
#define B_   2
#define T_   2048
#define E_   2048
#define H_   16
#define HKV_ 4
#define D_   128
#define ROWS (B_ * T_)          // 4096
#define QCOLS (H_ * D_)         // 2048
#define KCOLS (HKV_ * D_)       // 512

// ---------------------------------------------------------------------------
// Scratch (allocation-free: device globals). All working tensors fp16.
// Weights transposed [N][K]. V stored TRANSPOSED: Vt[d'][token].
// ---------------------------------------------------------------------------
__device__ __align__(1024) __half g_xh [(size_t)ROWS * E_];
__device__ __align__(1024) __half g_WqT[(size_t)QCOLS * E_];
__device__ __align__(1024) __half g_WkT[(size_t)KCOLS * E_];
__device__ __align__(1024) __half g_WvT[(size_t)KCOLS * E_];
__device__ __align__(1024) __half g_WoT[(size_t)E_ * QCOLS];
__device__ __align__(1024) __half g_Q  [(size_t)ROWS * QCOLS];
__device__ __align__(1024) __half g_K  [(size_t)ROWS * KCOLS];
__device__ __align__(1024) __half g_Vt [(size_t)KCOLS * ROWS];   // [512][4096]
__device__ __align__(1024) __half g_ctx[(size_t)ROWS * QCOLS];
__device__ __align__(1024) float  g_rcos[T_ * 64];
__device__ __align__(1024) float  g_rsin[T_ * 64];

// ---------------------------------------------------------------------------
// Helpers
// ---------------------------------------------------------------------------
__device__ __forceinline__ uint32_t smem_u32(const void* p) {
    uint32_t a;
    asm("{ .reg .u64 t; cvta.to.shared.u64 t, %1; cvt.u32.u64 %0, t; }" : "=r"(a) : "l"(p));
    return a;
}
__device__ __forceinline__ void cp_async16(uint32_t saddr, const void* gptr) {
    asm volatile("cp.async.cg.shared.global [%0], [%1], 16;" :: "r"(saddr), "l"(gptr));
}
#define CP_COMMIT() asm volatile("cp.async.commit_group;" ::: "memory")
#define CP_WAIT(n)  asm volatile("cp.async.wait_group %0;" :: "n"(n) : "memory")

__device__ __forceinline__ uint32_t h2_bits(float a, float b) {
    __half2 h = __floats2half2_rn(a, b);
    return *(uint32_t*)&h;
}
__device__ __forceinline__ float2 h2_floats(uint32_t w) {
    __half2 h = *(__half2*)&w;
    return __half22float2(h);
}

// fp16 MMA: m16n8k16, fp32 accumulate.
__device__ __forceinline__ void mma_h(float* c, const uint32_t* a, const uint32_t* b) {
    asm volatile(
        "mma.sync.aligned.m16n8k16.row.col.f32.f16.f16.f32 "
        "{%0,%1,%2,%3}, {%4,%5,%6,%7}, {%8,%9}, {%0,%1,%2,%3};"
        : "+f"(c[0]), "+f"(c[1]), "+f"(c[2]), "+f"(c[3])
        : "r"(a[0]), "r"(a[1]), "r"(a[2]), "r"(a[3]), "r"(b[0]), "r"(b[1]));
}

// ---------------------------------------------------------------------------
// Rope cos/sin table (double-precision source, fp32 table).
// ---------------------------------------------------------------------------
__global__ void rope_table(float* __restrict__ ct, float* __restrict__ st) {
    int idx = blockIdx.x * blockDim.x + threadIdx.x;
    if (idx >= T_ * 64) return;
    int t = idx >> 6, i = idx & 63;
    double w = pow(10000.0, -(double)i / 64.0);
    double ds, dc;
    sincos((double)t * w, &ds, &dc);
    ct[idx] = (float)dc;
    st[idx] = (float)ds;
}

// ---------------------------------------------------------------------------
// prep_xh: fp32 -> fp16 RN copy of x, 8 elements per thread.
// ---------------------------------------------------------------------------
__global__ void prep_xh(const float4* __restrict__ in, uint4* __restrict__ out, int n8) {
    int i = blockIdx.x * blockDim.x + threadIdx.x;
    if (i >= n8) return;
    float4 a = in[2 * i], b = in[2 * i + 1];
    uint4 o;
    o.x = h2_bits(a.x, a.y); o.y = h2_bits(a.z, a.w);
    o.z = h2_bits(b.x, b.y); o.w = h2_bits(b.z, b.w);
    out[i] = o;
}

// ---------------------------------------------------------------------------
// prep_trans: transpose + fp16 RN of all 4 weights. in[K][N] fp32 -> out[N][K] fp16.
// ---------------------------------------------------------------------------
__global__ void prep_trans(const float* __restrict__ wq, const float* __restrict__ wk,
                           const float* __restrict__ wv, const float* __restrict__ wo,
                           __half* wqt, __half* wkt, __half* wvt, __half* wot) {
    __shared__ float t[32][33];
    int idx = blockIdx.x;
    const float* in; __half* out; int K, N;
    if      (idx < 4096) { in = wq; out = wqt; K = E_;    N = QCOLS; }
    else if (idx < 5120) { in = wk; out = wkt; K = E_;    N = KCOLS; idx -= 4096; }
    else if (idx < 6144) { in = wv; out = wvt; K = E_;    N = KCOLS; idx -= 5120; }
    else                 { in = wo; out = wot; K = QCOLS; N = E_;    idx -= 6144; }
    int nb = N >> 5;
    int kb = idx / nb, jb = idx - kb * nb;
    int k0 = kb * 32, n0 = jb * 32;
    int tx = threadIdx.x, ty = threadIdx.y;
    for (int i = ty; i < 32; i += 8)
        t[i][tx] = in[(size_t)(k0 + i) * N + n0 + tx];
    __syncthreads();
    for (int i = ty; i < 32; i += 8)
        out[(size_t)(n0 + i) * K + k0 + tx] = __float2half_rn(t[tx][i]);
}

// ---------------------------------------------------------------------------
// FP16 mma.sync GEMM. C[M,N] = A[M,K] @ Bt[N,K]^T, A/B fp16 [.][K].
// CTA tile 128x256, chunk K=64 fp16 (32 words), 8 warps 2(m)x4(n), warp 64x64.
// 3-stage cp.async. mode: 0 fp32 plain store, 1 fp16 round store,
// 2 rope+1/sqrt(D)->fp16 (Q), 3 rope->fp16 (K).
// ---------------------------------------------------------------------------
#define GBM 128
#define GBN 256
#define GBKH 64                 // fp16 elements per chunk
#define GAST 36                 // word stride
#define GSTAGES 3
#define GA_W (GBM * GAST)       // 4608
#define GB_W (GBN * GAST)       // 9216
#define GSTAGE_W (GA_W + GB_W)  // 13824
#define GSMEM_BYTES (GSTAGES * GSTAGE_W * 4)   // 165888

__global__ __launch_bounds__(256, 1) void gemm_h(
    const __half* __restrict__ A,
    const __half* __restrict__ B1, void* __restrict__ C1, int mode1, int nblk1, int N1,
    const __half* __restrict__ B2, void* __restrict__ C2, int mode2, int N2,
    int K, const float* __restrict__ ct, const float* __restrict__ st)
{
    extern __shared__ __align__(16) uint32_t smw[];
    const int tid = threadIdx.x;
    const int wid = tid >> 5, lane = tid & 31;
    const int warpM = wid & 1, warpN = wid >> 1;
    const int bx = blockIdx.x;

    const __half* Bw; void* C; int mode, n0, N;
    if (bx < nblk1) { Bw = B1; C = C1; mode = mode1; N = N1; n0 = bx * GBN; }
    else            { Bw = B2; C = C2; mode = mode2; N = N2; n0 = (bx - nblk1) * GBN; }

    const int m0 = blockIdx.y * GBM;
    const int nch = K / GBKH;
    const int lr = lane >> 2, lc = lane & 3;

    float acc[4][8][4];
#pragma unroll
    for (int i = 0; i < 4; i++)
#pragma unroll
        for (int j = 0; j < 8; j++)
#pragma unroll
            for (int q = 0; q < 4; q++) acc[i][j][q] = 0.f;

    auto load_chunk = [&](int c, int s) {
        uint32_t as_base = smem_u32(smw + s * GSTAGE_W);
        uint32_t bs_base = as_base + GA_W * 4;
        // A: 128 rows x 8 chunks of 16B (8 fp16)
#pragma unroll
        for (int i = 0; i < 4; i++) {
            int ci = tid + i * 256;
            int row = ci >> 3, ch = ci & 7;
            cp_async16(as_base + (row * GAST + ch * 4) * 4,
                       A + (size_t)(m0 + row) * K + c * GBKH + ch * 8);
        }
        // B: 256 rows x 8 chunks
#pragma unroll
        for (int i = 0; i < 8; i++) {
            int ci = tid + i * 256;
            int row = ci >> 3, ch = ci & 7;
            cp_async16(bs_base + (row * GAST + ch * 4) * 4,
                       Bw + (size_t)(n0 + row) * K + c * GBKH + ch * 8);
        }
    };

#pragma unroll
    for (int s = 0; s < GSTAGES - 1; s++) { load_chunk(s, s); CP_COMMIT(); }

    for (int c = 0; c < nch; c++) {
        CP_WAIT(GSTAGES - 2);
        __syncthreads();

        int pc = c + GSTAGES - 1;
        if (pc < nch) load_chunk(pc, pc % GSTAGES);
        CP_COMMIT();

        const uint32_t* Asu = smw + (c % GSTAGES) * GSTAGE_W;
        const uint32_t* Bsu = Asu + GA_W;

#pragma unroll
        for (int kk = 0; kk < 4; kk++) {       // 4 x k16 = 64 fp16
            uint32_t afr[4][4], bfr[8][2];
#pragma unroll
            for (int mt = 0; mt < 4; mt++) {
                int row = warpM * 64 + mt * 16 + lr;
                int col = kk * 8 + lc;
                afr[mt][0] = Asu[row * GAST + col];
                afr[mt][1] = Asu[(row + 8) * GAST + col];
                afr[mt][2] = Asu[row * GAST + col + 4];
                afr[mt][3] = Asu[(row + 8) * GAST + col + 4];
            }
#pragma unroll
            for (int nt = 0; nt < 8; nt++) {
                int n = warpN * 64 + nt * 8 + lr;
                int k = kk * 8 + lc;
                bfr[nt][0] = Bsu[n * GAST + k];
                bfr[nt][1] = Bsu[n * GAST + k + 4];
            }
#pragma unroll
            for (int mt = 0; mt < 4; mt++)
#pragma unroll
                for (int nt = 0; nt < 8; nt++)
                    mma_h(acc[mt][nt], afr[mt], bfr[nt]);
        }
    }

    // ---- fused epilogue ----
#pragma unroll
    for (int mt = 0; mt < 4; mt++) {
        int rbase = m0 + warpM * 64 + mt * 16 + lr;
#pragma unroll
        for (int nt = 0; nt < 8; nt++) {
            int cbase = n0 + warpN * 64 + nt * 8 + lc * 2;
            float4 v = make_float4(acc[mt][nt][0], acc[mt][nt][1],
                                   acc[mt][nt][2], acc[mt][nt][3]);
            if (mode >= 2) {
                int i  = (cbase & 127) >> 1;
                int t0 = rbase & (T_ - 1);
                int t1 = (rbase + 8) & (T_ - 1);
                float c0 = ct[(t0 << 6) + i], s0 = st[(t0 << 6) + i];
                float c1 = ct[(t1 << 6) + i], s1 = st[(t1 << 6) + i];
                float scale = (mode == 2) ? 0.08838834764831845f : 1.0f;
                float x0 = (v.x * c0 - v.y * s0) * scale;
                float y0 = (v.x * s0 + v.y * c0) * scale;
                float x1 = (v.z * c1 - v.w * s1) * scale;
                float y1 = (v.z * s1 + v.w * c1) * scale;
                v = make_float4(x0, y0, x1, y1);
            }
            if (mode == 0) {
                float* Cf = (float*)C;
                *(float2*)(Cf + (size_t)rbase * N + cbase)       = make_float2(v.x, v.y);
                *(float2*)(Cf + (size_t)(rbase + 8) * N + cbase) = make_float2(v.z, v.w);
            } else {
                __half* Ch = (__half*)C;
                *(uint32_t*)(Ch + (size_t)rbase * N + cbase)       = h2_bits(v.x, v.y);
                *(uint32_t*)(Ch + (size_t)(rbase + 8) * N + cbase) = h2_bits(v.z, v.w);
            }
        }
    }
}

// ---------------------------------------------------------------------------
// Causal flash attention, fp16 mma. FBM=128 (8 warps x 16 rows), BN=64 keys.
// Q frags in registers (8 k16 steps over D=128). K smem [64 keys][64w+4].
// V from Vt (transposed) smem [128 d][32w+4]. P packed fp16 per warp.
// K/V double-buffered via cp.async.
// ---------------------------------------------------------------------------
#define FBM 128
#define KWST 68
#define VWST 36
#define PWST 68
#define KS_W (2 * 64 * KWST)    // 8704
#define VS_W (2 * 128 * VWST)   // 9216
#define PS_W (8 * 16 * PWST)    // 8704
#define FA_SMEM_BYTES ((KS_W + VS_W + PS_W) * 4)   // 106496

__global__ __launch_bounds__(256, 1) void flash_h(const __half* __restrict__ Q,
                                                  const __half* __restrict__ Km,
                                                  const __half* __restrict__ Vt,
                                                  __half* __restrict__ ctx) {
    extern __shared__ __align__(16) uint32_t smw[];
    uint32_t* KsB = smw;
    uint32_t* VsB = smw + KS_W;
    uint32_t* PsB = VsB + VS_W;

    const int tid = threadIdx.x;
    const int wid = tid >> 5, lane = tid & 31;
    const int lr = lane >> 2, lc = lane & 3;
    const int m0 = (int)(gridDim.x - 1 - blockIdx.x) * FBM;   // heavy first
    const int h = blockIdx.y, b = blockIdx.z;
    const int kvh = h >> 2;

    uint32_t* Pw = PsB + wid * 16 * PWST;

    // ---- Q fragments (staged through P buffer) ----
    uint32_t qa[8][4];
    {
        const __half* qsrc = Q + (size_t)(b * T_ + m0 + wid * 16) * QCOLS + h * 128;
#pragma unroll
        for (int i = 0; i < 8; i++) {
            int task = lane + i * 32;           // 256 tasks: 16 rows x 16 chunks(8 fp16)
            int row = task >> 4, c4 = task & 15;
            uint4 v = *(const uint4*)(qsrc + (size_t)row * QCOLS + c4 * 8);
            *(uint4*)&Pw[row * PWST + c4 * 4] = v;
        }
        __syncwarp();
#pragma unroll
        for (int kk = 0; kk < 8; kk++) {
            qa[kk][0] = Pw[lr * PWST + kk * 8 + lc];
            qa[kk][1] = Pw[(lr + 8) * PWST + kk * 8 + lc];
            qa[kk][2] = Pw[lr * PWST + kk * 8 + lc + 4];
            qa[kk][3] = Pw[(lr + 8) * PWST + kk * 8 + lc + 4];
        }
        __syncwarp();
    }

    float oacc[16][4];
#pragma unroll
    for (int i = 0; i < 16; i++)
#pragma unroll
        for (int q = 0; q < 4; q++) oacc[i][q] = 0.f;
    float m_i[2] = {-1e30f, -1e30f};
    float l_i[2] = {0.f, 0.f};

    const int ntiles = m0 / 64 + 2;

    auto load_kv = [&](int t, int stg) {
        const __half* kb = Km + (size_t)(b * T_ + t * 64) * KCOLS + kvh * 128;
        const __half* vb = Vt + (size_t)(kvh * 128) * ROWS + b * T_ + t * 64;
        uint32_t ka = smem_u32(KsB + stg * 64 * KWST);
        uint32_t va = smem_u32(VsB + stg * 128 * VWST);
        // K: 64 keys x 16 chunks of 16B (128 fp16 per key)
#pragma unroll
        for (int i = 0; i < 4; i++) {
            int task = tid + i * 256;           // 1024 tasks
            int key = task >> 4, ch = task & 15;
            cp_async16(ka + (key * KWST + ch * 4) * 4, kb + (size_t)key * KCOLS + ch * 8);
        }
        // V: 128 d-rows x 8 chunks of 16B (64 keys per row, contiguous in Vt)
#pragma unroll
        for (int i = 0; i < 4; i++) {
            int task = tid + i * 256;           // 1024 tasks
            int row = task >> 3, ch = task & 7;
            cp_async16(va + (row * VWST + ch * 4) * 4, vb + (size_t)row * ROWS + ch * 8);
        }
    };

    load_kv(0, 0);
    CP_COMMIT();

    for (int t = 0; t < ntiles; t++) {
        if (t + 1 < ntiles) { load_kv(t + 1, (t + 1) & 1); CP_COMMIT(); CP_WAIT(1); }
        else                { CP_WAIT(0); }
        __syncthreads();

        const uint32_t* Kw = KsB + (t & 1) * 64 * KWST;
        const uint32_t* Vw = VsB + (t & 1) * 128 * VWST;

        // ---- S = Q K^T (8 k16 steps over D) ----
        float sacc[8][4];
#pragma unroll
        for (int nt = 0; nt < 8; nt++)
#pragma unroll
            for (int q = 0; q < 4; q++) sacc[nt][q] = 0.f;

#pragma unroll
        for (int kk = 0; kk < 8; kk++) {
            uint32_t bfr[8][2];
#pragma unroll
            for (int nt = 0; nt < 8; nt++) {
                bfr[nt][0] = Kw[(nt * 8 + lr) * KWST + kk * 8 + lc];
                bfr[nt][1] = Kw[(nt * 8 + lr) * KWST + kk * 8 + lc + 4];
            }
#pragma unroll
            for (int nt = 0; nt < 8; nt++)
                mma_h(sacc[nt], qa[kk], bfr[nt]);
        }

        // ---- causal mask ----
        const int row0g = m0 + wid * 16 + lr;
        const int row1g = row0g + 8;
        if (t * 64 + 63 > m0 + wid * 16) {
#pragma unroll
            for (int nt = 0; nt < 8; nt++) {
                int colg = t * 64 + nt * 8 + 2 * lc;
                if (colg     > row0g) sacc[nt][0] = -1e30f;
                if (colg + 1 > row0g) sacc[nt][1] = -1e30f;
                if (colg     > row1g) sacc[nt][2] = -1e30f;
                if (colg + 1 > row1g) sacc[nt][3] = -1e30f;
            }
        }

        // ---- online softmax ----
        float rmax0 = -1e30f, rmax1 = -1e30f;
#pragma unroll
        for (int nt = 0; nt < 8; nt++) {
            rmax0 = fmaxf(rmax0, fmaxf(sacc[nt][0], sacc[nt][1]));
            rmax1 = fmaxf(rmax1, fmaxf(sacc[nt][2], sacc[nt][3]));
        }
        rmax0 = fmaxf(rmax0, __shfl_xor_sync(0xffffffffu, rmax0, 1));
        rmax0 = fmaxf(rmax0, __shfl_xor_sync(0xffffffffu, rmax0, 2));
        rmax1 = fmaxf(rmax1, __shfl_xor_sync(0xffffffffu, rmax1, 1));
        rmax1 = fmaxf(rmax1, __shfl_xor_sync(0xffffffffu, rmax1, 2));

        float mnew0 = fmaxf(m_i[0], rmax0);
        float mnew1 = fmaxf(m_i[1], rmax1);
        float alpha0 = __expf(m_i[0] - mnew0);
        float alpha1 = __expf(m_i[1] - mnew1);

        float rsum0 = 0.f, rsum1 = 0.f;
#pragma unroll
        for (int nt = 0; nt < 8; nt++) {
            uint32_t w0 = h2_bits(__expf(sacc[nt][0] - mnew0), __expf(sacc[nt][1] - mnew0));
            uint32_t w1 = h2_bits(__expf(sacc[nt][2] - mnew1), __expf(sacc[nt][3] - mnew1));
            float2 p0 = h2_floats(w0);   // the exact fp16 values fed to PV
            float2 p1 = h2_floats(w1);
            rsum0 += p0.x + p0.y;
            rsum1 += p1.x + p1.y;
            Pw[lr * PWST + nt * 4 + lc]       = w0;
            Pw[(lr + 8) * PWST + nt * 4 + lc] = w1;
        }
        rsum0 += __shfl_xor_sync(0xffffffffu, rsum0, 1);
        rsum0 += __shfl_xor_sync(0xffffffffu, rsum0, 2);
        rsum1 += __shfl_xor_sync(0xffffffffu, rsum1, 1);
        rsum1 += __shfl_xor_sync(0xffffffffu, rsum1, 2);

        l_i[0] = l_i[0] * alpha0 + rsum0;
        l_i[1] = l_i[1] * alpha1 + rsum1;
        m_i[0] = mnew0;
        m_i[1] = mnew1;
#pragma unroll
        for (int nt = 0; nt < 16; nt++) {
            oacc[nt][0] *= alpha0; oacc[nt][1] *= alpha0;
            oacc[nt][2] *= alpha1; oacc[nt][3] *= alpha1;
        }
        __syncwarp();

        // ---- O += P V  (4 k16 steps over 64 keys; V from Vt, d-major) ----
#pragma unroll
        for (int kk = 0; kk < 4; kk++) {
            uint32_t pa[4];
            pa[0] = Pw[lr * PWST + kk * 8 + lc];
            pa[1] = Pw[(lr + 8) * PWST + kk * 8 + lc];
            pa[2] = Pw[lr * PWST + kk * 8 + lc + 4];
            pa[3] = Pw[(lr + 8) * PWST + kk * 8 + lc + 4];
#pragma unroll
            for (int nt = 0; nt < 16; nt++) {
                uint32_t bfr[2];
                bfr[0] = Vw[(nt * 8 + lr) * VWST + kk * 8 + lc];
                bfr[1] = Vw[(nt * 8 + lr) * VWST + kk * 8 + lc + 4];
                mma_h(oacc[nt], pa, bfr);
            }
        }
        __syncwarp();
        __syncthreads();
    }

    // ---- epilogue: normalize, fp16 store ----
    float inv0 = 1.0f / l_i[0];
    float inv1 = 1.0f / l_i[1];
    const int row0g = m0 + wid * 16 + lr;
    __half* c0 = ctx + (size_t)(b * T_ + row0g) * QCOLS + h * 128;
    __half* c1 = ctx + (size_t)(b * T_ + row0g + 8) * QCOLS + h * 128;
#pragma unroll
    for (int nt = 0; nt < 16; nt++) {
        int col = nt * 8 + 2 * lc;
        *(uint32_t*)(c0 + col) = h2_bits(oacc[nt][0] * inv0, oacc[nt][1] * inv0);
        *(uint32_t*)(c1 + col) = h2_bits(oacc[nt][2] * inv1, oacc[nt][3] * inv1);
    }
}

// ---------------------------------------------------------------------------
// Host
// ---------------------------------------------------------------------------
extern "C" void kernel_launch(void* const* d_in, const int* in_sizes, int n_in,
                              void* d_out, int out_size) {
    const float* x    = (const float*)d_in[0];
    const float* Wq   = (const float*)d_in[1];
    const float* Wk   = (const float*)d_in[2];
    const float* Wv   = (const float*)d_in[3];
    const float* Wout = (const float*)d_in[4];
    float* out = (float*)d_out;

    __half *xh, *WqT, *WkT, *WvT, *WoT, *Qb, *Kb, *Vtb, *Cb;
    float *ctab, *stab;
    cudaGetSymbolAddress((void**)&xh,  g_xh);
    cudaGetSymbolAddress((void**)&WqT, g_WqT);
    cudaGetSymbolAddress((void**)&WkT, g_WkT);
    cudaGetSymbolAddress((void**)&WvT, g_WvT);
    cudaGetSymbolAddress((void**)&WoT, g_WoT);
    cudaGetSymbolAddress((void**)&Qb,  g_Q);
    cudaGetSymbolAddress((void**)&Kb,  g_K);
    cudaGetSymbolAddress((void**)&Vtb, g_Vt);
    cudaGetSymbolAddress((void**)&Cb,  g_ctx);
    cudaGetSymbolAddress((void**)&ctab, g_rcos);
    cudaGetSymbolAddress((void**)&stab, g_rsin);

    cudaFuncSetAttribute(gemm_h,  cudaFuncAttributeMaxDynamicSharedMemorySize, GSMEM_BYTES);
    cudaFuncSetAttribute(flash_h, cudaFuncAttributeMaxDynamicSharedMemorySize, FA_SMEM_BYTES);

    // 1) prep: x -> fp16, weights -> transposed fp16
    prep_xh<<<(ROWS * E_ / 8 + 255) / 256, 256>>>((const float4*)x, (uint4*)xh, ROWS * E_ / 8);
    prep_trans<<<10240, dim3(32, 8)>>>(Wq, Wk, Wv, Wout, WqT, WkT, WvT, WoT);

    // 2) rope table
    rope_table<<<(T_ * 64 + 255) / 256, 256>>>(ctab, stab);

    // 3) Q + K projections fused (grid.x = 8 + 2 = 10)
    gemm_h<<<dim3(10, ROWS / GBM), 256, GSMEM_BYTES>>>(
        xh,
        WqT, Qb, 2, QCOLS / GBN, QCOLS,    // Q: rope + 1/sqrt(D) -> fp16
        WkT, Kb, 3, KCOLS,                 // K: rope -> fp16
        E_, ctab, stab);

    // 4) V^T = WvT @ x^T : A = WvT [512][2048], B = x_h ([4096][2048] as [N][K]),
    //    C = Vt [512][4096] fp16. grid (16, 4).
    gemm_h<<<dim3(ROWS / GBN, KCOLS / GBM), 256, GSMEM_BYTES>>>(
        WvT,
        xh, Vtb, 1, ROWS / GBN, ROWS,
        xh, Vtb, 1, ROWS,
        E_, ctab, stab);

    // 5) attention (fp16 flash)
    flash_h<<<dim3(T_ / FBM, H_, B_), 256, FA_SMEM_BYTES>>>(Qb, Kb, Vtb, Cb);

    // 6) output projection: A = ctx fp16, C = out fp32. grid (8, 32).
    gemm_h<<<dim3(E_ / GBN, ROWS / GBM), 256, GSMEM_BYTES>>>(
        Cb,
        WoT, out, 0, E_ / GBN, E_,
        WoT, out, 0, E_,
        QCOLS, ctab, stab);
}